// round 1
// baseline (speedup 1.0000x reference)
#include <cuda_runtime.h>

// Problem constants
#define B_SZ  4
#define SEQ   4096
#define HIDN  1024
#define NH    16
#define HD    64
#define MTOT  (B_SZ * SEQ)   // 16384 tokens

// Scratch (device globals: no allocations allowed in kernel_launch)
static __device__ float g_q[(size_t)MTOT * HIDN];
static __device__ float g_k[(size_t)MTOT * HIDN];
static __device__ float g_v[(size_t)MTOT * HIDN];
static __device__ float g_x[(size_t)MTOT * HIDN];

// ---------------------------------------------------------------------------
// SGEMM: C[M,N] = A[M,K] @ W[K,N] + bias[N]   (all row-major, fp32)
// 128x128 block tile, BK=16, 256 threads, 8x8 per-thread tile,
// double-buffered shared memory with register-staged global prefetch.
// ---------------------------------------------------------------------------
#define BM 128
#define BN 128
#define BK 16

__global__ __launch_bounds__(256, 2)
void sgemm_bias(const float* __restrict__ A, const float* __restrict__ W,
                const float* __restrict__ bias, float* __restrict__ C,
                int M, int N, int K)
{
    __shared__ float As[2][BK][BM];
    __shared__ float Bs[2][BK][BN];

    const int tid = threadIdx.x;
    const int tx  = tid & 15;   // 0..15  -> column group
    const int ty  = tid >> 4;   // 0..15  -> row group
    const int row0 = blockIdx.y * BM;
    const int col0 = blockIdx.x * BN;

    // Global-load mapping
    const int a_r = tid >> 2;          // 0..63   (A tile rows, +64 for 2nd half)
    const int a_k = (tid & 3) << 2;    // 0,4,8,12 (A tile K offset, float4)
    const int b_r = tid >> 5;          // 0..7    (W tile rows, +8 for 2nd half)
    const int b_c = (tid & 31) << 2;   // 0..124  (W tile cols, float4)

    const float* Ab = A + (size_t)row0 * K;

    float acc[8][8];
#pragma unroll
    for (int i = 0; i < 8; i++)
#pragma unroll
        for (int j = 0; j < 8; j++) acc[i][j] = 0.f;

    // Prologue: load tile 0 into buffer 0
    {
        float4 a0 = *(const float4*)(Ab + (size_t)a_r * K + a_k);
        float4 a1 = *(const float4*)(Ab + (size_t)(a_r + 64) * K + a_k);
        float4 w0 = *(const float4*)(W + (size_t)b_r * N + col0 + b_c);
        float4 w1 = *(const float4*)(W + (size_t)(b_r + 8) * N + col0 + b_c);
        As[0][a_k + 0][a_r] = a0.x; As[0][a_k + 1][a_r] = a0.y;
        As[0][a_k + 2][a_r] = a0.z; As[0][a_k + 3][a_r] = a0.w;
        As[0][a_k + 0][a_r + 64] = a1.x; As[0][a_k + 1][a_r + 64] = a1.y;
        As[0][a_k + 2][a_r + 64] = a1.z; As[0][a_k + 3][a_r + 64] = a1.w;
        *(float4*)&Bs[0][b_r][b_c]     = w0;
        *(float4*)&Bs[0][b_r + 8][b_c] = w1;
    }
    __syncthreads();

    const int NT = K / BK;
    for (int kt = 0; kt < NT; kt++) {
        const int cur = kt & 1;

        float4 a0, a1, w0, w1;
        const bool more = (kt + 1 < NT);
        if (more) {
            const float* Ap = Ab + (size_t)(kt + 1) * BK;
            a0 = *(const float4*)(Ap + (size_t)a_r * K + a_k);
            a1 = *(const float4*)(Ap + (size_t)(a_r + 64) * K + a_k);
            const float* Wp = W + (size_t)(kt + 1) * BK * N + col0;
            w0 = *(const float4*)(Wp + (size_t)b_r * N + b_c);
            w1 = *(const float4*)(Wp + (size_t)(b_r + 8) * N + b_c);
        }

#pragma unroll
        for (int kk = 0; kk < BK; kk++) {
            float ar[8], br[8];
            *(float4*)(ar)     = *(const float4*)&As[cur][kk][ty * 8];
            *(float4*)(ar + 4) = *(const float4*)&As[cur][kk][ty * 8 + 4];
            *(float4*)(br)     = *(const float4*)&Bs[cur][kk][tx * 8];
            *(float4*)(br + 4) = *(const float4*)&Bs[cur][kk][tx * 8 + 4];
#pragma unroll
            for (int i = 0; i < 8; i++)
#pragma unroll
                for (int j = 0; j < 8; j++)
                    acc[i][j] += ar[i] * br[j];
        }

        if (more) {
            const int nxt = cur ^ 1;
            As[nxt][a_k + 0][a_r] = a0.x; As[nxt][a_k + 1][a_r] = a0.y;
            As[nxt][a_k + 2][a_r] = a0.z; As[nxt][a_k + 3][a_r] = a0.w;
            As[nxt][a_k + 0][a_r + 64] = a1.x; As[nxt][a_k + 1][a_r + 64] = a1.y;
            As[nxt][a_k + 2][a_r + 64] = a1.z; As[nxt][a_k + 3][a_r + 64] = a1.w;
            *(float4*)&Bs[nxt][b_r][b_c]     = w0;
            *(float4*)&Bs[nxt][b_r + 8][b_c] = w1;
        }
        __syncthreads();
    }

    // Epilogue: add bias, vectorized stores
#pragma unroll
    for (int i = 0; i < 8; i++) {
        const size_t r = (size_t)(row0 + ty * 8 + i);
#pragma unroll
        for (int j4 = 0; j4 < 8; j4 += 4) {
            const int c = col0 + tx * 8 + j4;
            float4 o;
            o.x = acc[i][j4 + 0] + bias[c + 0];
            o.y = acc[i][j4 + 1] + bias[c + 1];
            o.z = acc[i][j4 + 2] + bias[c + 2];
            o.w = acc[i][j4 + 3] + bias[c + 3];
            *(float4*)&C[r * N + c] = o;
        }
    }
}

// ---------------------------------------------------------------------------
// Per-token attention over the HEADS axis (reference never transposes):
// one block per (b,s) token, 256 threads.
// Scores: w0 * qk/8 + w1 * qk/max(|q||k|,eps) + w2 * (-sqrt(max(|q|^2+|k|^2-2qk,0)))
// Softmax over j, out = attn @ v, written to xperm with the
// transpose(1,2).reshape fold: row = h*256 + s/16, col = (s%16)*64 + d.
// ---------------------------------------------------------------------------
#define PD 68   // padded row (16B-aligned, reduces LDS bank conflicts)

__global__ __launch_bounds__(256)
void attn_kernel(const float* __restrict__ q, const float* __restrict__ k,
                 const float* __restrict__ v, const float* __restrict__ sw,
                 float* __restrict__ xperm, float* __restrict__ attn_out,
                 int write_attn)
{
    __shared__ float sq[NH][PD], sk[NH][PD], sv[NH][PD];
    __shared__ float s_qk[NH][NH];
    __shared__ float s_qn2[NH], s_kn2[NH];
    __shared__ float s_at[NH][NH + 1];

    const int t   = blockIdx.x;
    const int b   = t >> 12;     // / 4096
    const int s   = t & 4095;
    const int tid = threadIdx.x;
    const size_t base = (size_t)t * HIDN;

    // Load q/k/v for this token: 16 heads x 64
    {
        const int row = tid >> 4;          // 0..15
        const int col = (tid & 15) << 2;   // 0..60
        *(float4*)&sq[row][col] = *(const float4*)(q + base + row * HD + col);
        *(float4*)&sk[row][col] = *(const float4*)(k + base + row * HD + col);
        *(float4*)&sv[row][col] = *(const float4*)(v + base + row * HD + col);
    }
    __syncthreads();

    // Self-dots (squared norms)
    if (tid < 32) {
        const int i = tid & 15;
        const float* p = (tid < 16) ? sq[i] : sk[i];
        float ss = 0.f;
#pragma unroll
        for (int d = 0; d < HD; d++) ss += p[d] * p[d];
        if (tid < 16) s_qn2[i] = ss; else s_kn2[i] = ss;
    }
    // qk[i][j] = q_i . k_j  (one thread per pair)
    {
        const int i = tid >> 4, j = tid & 15;
        float dot = 0.f;
#pragma unroll
        for (int d = 0; d < HD; d++) dot += sq[i][d] * sk[j][d];
        s_qk[i][j] = dot;
    }
    __syncthreads();

    // Scores + row softmax: one thread per query head
    if (tid < NH) {
        float w0, w1, w2;
        {
            const float x0 = sw[0], x1 = sw[1], x2 = sw[2];
            const float m  = fmaxf(x0, fmaxf(x1, x2));
            const float e0 = expf(x0 - m), e1 = expf(x1 - m), e2 = expf(x2 - m);
            const float inv = 1.f / (e0 + e1 + e2);
            w0 = e0 * inv; w1 = e1 * inv; w2 = e2 * inv;
        }
        const int i = tid;
        const float qn2 = s_qn2[i];
        const float qn  = sqrtf(qn2);
        float sc[NH];
        float mx = -1e30f;
#pragma unroll
        for (int j = 0; j < NH; j++) {
            const float qkv  = s_qk[i][j];
            const float kn2  = s_kn2[j];
            const float dotv = qkv * 0.125f;                              // / sqrt(64)
            const float cosv = qkv / fmaxf(qn * sqrtf(kn2), 1e-8f);
            const float d2   = fmaxf(qn2 + kn2 - 2.f * qkv, 0.f);
            const float dstv = -sqrtf(d2);
            const float scv  = w0 * dotv + w1 * cosv + w2 * dstv;
            sc[j] = scv;
            mx = fmaxf(mx, scv);
        }
        float ssum = 0.f;
#pragma unroll
        for (int j = 0; j < NH; j++) { const float e = expf(sc[j] - mx); sc[j] = e; ssum += e; }
        const float inv = 1.f / ssum;
#pragma unroll
        for (int j = 0; j < NH; j++) {
            const float a = sc[j] * inv;
            s_at[i][j] = a;
            if (write_attn)
                attn_out[(size_t)t * (NH * NH) + i * NH + j] = a;
        }
    }
    __syncthreads();

    // out[i][d] = sum_j attn[i][j] * v[j][d]; write permuted for final GEMM
    {
        const int i  = tid >> 4;           // query head
        const int db = (tid & 15) << 2;    // d base (float4)
        float4 o = make_float4(0.f, 0.f, 0.f, 0.f);
#pragma unroll
        for (int j = 0; j < NH; j++) {
            const float a = s_at[i][j];
            const float4 vv = *(const float4*)&sv[j][db];
            o.x += a * vv.x; o.y += a * vv.y; o.z += a * vv.z; o.w += a * vv.w;
        }
        // transpose(1,2).reshape fold: row = h*256 + s/16, col = (s%16)*64 + d
        const size_t dst = (size_t)b * ((size_t)SEQ * HIDN)
                         + (size_t)((i << 8) + (s >> 4)) * HIDN
                         + (size_t)((s & 15) << 6) + db;
        *(float4*)&xperm[dst] = o;
    }
}

// ---------------------------------------------------------------------------
extern "C" void kernel_launch(void* const* d_in, const int* in_sizes, int n_in,
                              void* d_out, int out_size)
{
    const float* query = (const float*)d_in[0];
    const float* key_  = (const float*)d_in[1];
    const float* value = (const float*)d_in[2];
    const float* Wq    = (const float*)d_in[3];
    const float* bq    = (const float*)d_in[4];
    const float* Wk    = (const float*)d_in[5];
    const float* bk    = (const float*)d_in[6];
    const float* Wv    = (const float*)d_in[7];
    const float* bv    = (const float*)d_in[8];
    const float* Wo    = (const float*)d_in[9];
    const float* bo    = (const float*)d_in[10];
    const float* sw    = (const float*)d_in[11];
    float* out = (float*)d_out;

    float *gq, *gk, *gv, *gx;
    cudaGetSymbolAddress((void**)&gq, g_q);
    cudaGetSymbolAddress((void**)&gk, g_k);
    cudaGetSymbolAddress((void**)&gv, g_v);
    cudaGetSymbolAddress((void**)&gx, g_x);

    dim3 gg(HIDN / BN, MTOT / BM);
    sgemm_bias<<<gg, 256>>>(query, Wq, bq, gq, MTOT, HIDN, HIDN);
    sgemm_bias<<<gg, 256>>>(key_,  Wk, bk, gk, MTOT, HIDN, HIDN);
    sgemm_bias<<<gg, 256>>>(value, Wv, bv, gv, MTOT, HIDN, HIDN);

    const long long main_elems = (long long)MTOT * HIDN;                 // 16,777,216
    const long long attn_elems = (long long)MTOT * NH * NH;              //  4,194,304
    const int write_attn = ((long long)out_size >= main_elems + attn_elems) ? 1 : 0;
    float* attn_ptr = out + main_elems;

    attn_kernel<<<MTOT, 256>>>(gq, gk, gv, sw, gx, attn_ptr, write_attn);

    sgemm_bias<<<gg, 256>>>(gx, Wo, bo, out, MTOT, HIDN, HIDN);
}

// round 4
// speedup vs baseline: 3.4380x; 3.4380x over previous
#include <cuda_runtime.h>
#include <cstdint>

// Problem constants
#define B_SZ  4
#define SEQ   4096
#define HIDN  1024
#define NH    16
#define HD    64
#define MTOT  (B_SZ * SEQ)   // 16384 tokens

// Arch-feature gate: tcgen05/TMEM only legal in arch-specific ('a') passes.
#if defined(__CUDA_ARCH__) && (defined(__CUDA_ARCH_FEAT_SM103_ALL) || defined(__CUDA_ARCH_FEAT_SM100_ALL) || defined(__CUDA_ARCH_FEAT_SM101_ALL))
#define HAS_TC 1
#else
#define HAS_TC 0
#endif

// Scratch (device globals: no allocations allowed in kernel_launch)
static __device__ float g_q[(size_t)MTOT * HIDN];
static __device__ float g_k[(size_t)MTOT * HIDN];
static __device__ float g_v[(size_t)MTOT * HIDN];
static __device__ float g_x[(size_t)MTOT * HIDN];
static __device__ float g_wt[(size_t)4 * HIDN * HIDN];   // transposed weights [N][K] x4

// ===========================================================================
// GEMM tile geometry (tensor path)
// ===========================================================================
#define GBM 128
#define GBN 256
#define GBK 32
#define GKD 1024
#define GNCH (GKD / GBK)          // 32 chunks

#define SM_TMEM   0
#define SM_MBAR0  8
#define SM_MBAR1  16
#define SM_BUF    1024
#define BUF_STRIDE 98304          // 96 KB per buffer
#define OFF_AH 0
#define OFF_AL 16384
#define OFF_BH 32768
#define OFF_BL 65536
#define GEMM_SMEM_BYTES (1024 + 2 * BUF_STRIDE)   // 197632

#define IDESC_TF32 ((1u << 4) | (2u << 7) | (2u << 10) | ((GBN / 8) << 17) | ((GBM / 16) << 24))

extern __shared__ char dynsmem[];

#if HAS_TC
// ---------------------------------------------------------------------------
// tcgen05 helpers (sm_103a-only pass)
// ---------------------------------------------------------------------------
__device__ __forceinline__ uint32_t s2u(const void* p) {
    uint32_t a;
    asm("{ .reg .u64 t; cvta.to.shared.u64 t, %1; cvt.u32.u64 %0, t; }"
        : "=r"(a) : "l"(p));
    return a;
}

__device__ __forceinline__ bool elect1() {
    uint32_t p;
    asm volatile("{ .reg .pred p; elect.sync _|p, 0xFFFFFFFF; selp.b32 %0, 1, 0, p; }"
                 : "=r"(p));
    return p != 0;
}

__device__ __forceinline__ void mbar_init(uint32_t mbar, uint32_t cnt) {
    asm volatile("mbarrier.init.shared.b64 [%0], %1;" :: "r"(mbar), "r"(cnt) : "memory");
}

__device__ __forceinline__ void mbar_wait(uint32_t mbar, uint32_t parity) {
    asm volatile(
        "{\n\t"
        ".reg .pred P;\n\t"
        "WL%=:\n\t"
        "mbarrier.try_wait.parity.acquire.cta.shared::cta.b64 P, [%0], %1, 0x989680;\n\t"
        "@P bra.uni WD%=;\n\t"
        "bra.uni WL%=;\n\t"
        "WD%=:\n\t"
        "}"
        :: "r"(mbar), "r"(parity) : "memory");
}

__device__ __forceinline__ void tmem_alloc(uint32_t smem_dst, uint32_t ncols) {
    asm volatile("tcgen05.alloc.cta_group::1.sync.aligned.shared::cta.b32 [%0], %1;"
                 :: "r"(smem_dst), "r"(ncols) : "memory");
}
__device__ __forceinline__ void tmem_relinquish() {
    asm volatile("tcgen05.relinquish_alloc_permit.cta_group::1.sync.aligned;");
}
__device__ __forceinline__ void tmem_dealloc(uint32_t tmem, uint32_t ncols) {
    asm volatile("tcgen05.dealloc.cta_group::1.sync.aligned.b32 %0, %1;"
                 :: "r"(tmem), "r"(ncols));
}
__device__ __forceinline__ void tc_commit(uint32_t mbar) {
    asm volatile("tcgen05.commit.cta_group::1.mbarrier::arrive::one.shared::cluster.b64 [%0];"
                 :: "r"(mbar) : "memory");
}
__device__ __forceinline__ void tc_fence_after() {
    asm volatile("tcgen05.fence::after_thread_sync;" ::: "memory");
}
__device__ __forceinline__ void fence_async_smem() {
    asm volatile("fence.proxy.async.shared::cta;" ::: "memory");
}
__device__ __forceinline__ void tc_wait_ld() {
    asm volatile("tcgen05.wait::ld.sync.aligned;" ::: "memory");
}

// SS tf32 MMA, cta_group::1
__device__ __forceinline__ void mma_tf32(uint32_t d_tmem, uint64_t a_desc,
                                         uint64_t b_desc, uint32_t idesc, uint32_t en) {
    asm volatile(
        "{\n\t"
        ".reg .pred p;\n\t"
        "setp.ne.u32 p, %4, 0;\n\t"
        "tcgen05.mma.cta_group::1.kind::tf32 [%0], %1, %2, %3, {%5, %5, %5, %5}, p;\n\t"
        "}"
        :: "r"(d_tmem), "l"(a_desc), "l"(b_desc), "r"(idesc), "r"(en), "r"(0u)
        : "memory");
}

#define TC_LD_X32(r, addr)                                                     \
    asm volatile(                                                              \
        "tcgen05.ld.sync.aligned.32x32b.x32.b32 "                              \
        "{%0, %1, %2, %3, %4, %5, %6, %7, "                                    \
        " %8, %9, %10, %11, %12, %13, %14, %15, "                              \
        " %16, %17, %18, %19, %20, %21, %22, %23, "                            \
        " %24, %25, %26, %27, %28, %29, %30, %31}, [%32];"                     \
        : "=r"((r)[0]),  "=r"((r)[1]),  "=r"((r)[2]),  "=r"((r)[3]),           \
          "=r"((r)[4]),  "=r"((r)[5]),  "=r"((r)[6]),  "=r"((r)[7]),           \
          "=r"((r)[8]),  "=r"((r)[9]),  "=r"((r)[10]), "=r"((r)[11]),          \
          "=r"((r)[12]), "=r"((r)[13]), "=r"((r)[14]), "=r"((r)[15]),          \
          "=r"((r)[16]), "=r"((r)[17]), "=r"((r)[18]), "=r"((r)[19]),          \
          "=r"((r)[20]), "=r"((r)[21]), "=r"((r)[22]), "=r"((r)[23]),          \
          "=r"((r)[24]), "=r"((r)[25]), "=r"((r)[26]), "=r"((r)[27]),          \
          "=r"((r)[28]), "=r"((r)[29]), "=r"((r)[30]), "=r"((r)[31])           \
        : "r"(addr))

__device__ __forceinline__ float tf32_hi(float x) {
    uint32_t u;
    asm("cvt.rna.tf32.f32 %0, %1;" : "=r"(u) : "f"(x));
    return __uint_as_float(u);
}

#define SWZ(o) ((o) ^ (((o) >> 3) & 0x70))

// SW128 descriptor: layout=2<<61 | version=1<<46 | SBO=64<<32 | LBO=1<<16
__device__ __forceinline__ uint64_t mkdesc(uint32_t smem_addr) {
    return 0x4000404000010000ull | ((uint64_t)(smem_addr >> 4) & 0x3FFF);
}
#endif  // HAS_TC

// ===========================================================================
// GEMM: C[M,N] = A[M,K] @ WT[N,K]^T + bias, via 3xTF32 tcgen05.
// Body only exists in the arch-specific pass; stub elsewhere. The host side
// detects which one got loaded via cudaFuncGetAttributes().numRegs.
// ===========================================================================
__global__ __launch_bounds__(256, 1)
void gemm_tf32x3(const float* __restrict__ A, const float* __restrict__ WT,
                 const float* __restrict__ bias, float* __restrict__ C)
{
#if HAS_TC
    char* sm = dynsmem;
    const uint32_t sb  = s2u(dynsmem);
    const int tid  = threadIdx.x;
    const int row0 = blockIdx.y * GBM;
    const int col0 = blockIdx.x * GBN;

    if (tid < 32) {
        tmem_alloc(sb + SM_TMEM, 256);
        tmem_relinquish();
    }
    if (tid == 0) {
        mbar_init(sb + SM_MBAR0, 1);
        mbar_init(sb + SM_MBAR1, 1);
    }
    __syncthreads();

    uint32_t tmem;
    asm volatile("ld.shared.b32 %0, [%1];" : "=r"(tmem) : "r"(sb + SM_TMEM));

    int ph0 = 0, ph1 = 0;

    for (int kt = 0; kt < GNCH; kt++) {
        const int bsel = kt & 1;
        char* buf = sm + SM_BUF + bsel * BUF_STRIDE;
        const uint32_t bufu = sb + SM_BUF + bsel * BUF_STRIDE;

        // ---- global loads into registers (prefetch; overlaps prior MMA) ----
        float4 av[4], bv[8];
#pragma unroll
        for (int i = 0; i < 4; i++) {
            const int idx = tid + 256 * i;
            const int r = idx >> 3, c4 = idx & 7;
            av[i] = *(const float4*)(A + (size_t)(row0 + r) * GKD + kt * GBK + c4 * 4);
        }
#pragma unroll
        for (int i = 0; i < 8; i++) {
            const int idx = tid + 256 * i;
            const int r = idx >> 3, c4 = idx & 7;
            bv[i] = *(const float4*)(WT + (size_t)(col0 + r) * GKD + kt * GBK + c4 * 4);
        }

        // ---- wait for the MMA group that last read this buffer ----
        if (kt >= 2) {
            if (bsel == 0) { mbar_wait(sb + SM_MBAR0, ph0 & 1); ph0++; }
            else           { mbar_wait(sb + SM_MBAR1, ph1 & 1); ph1++; }
        }

        // ---- split hi/lo + swizzled STS ----
#pragma unroll
        for (int i = 0; i < 4; i++) {
            const int idx = tid + 256 * i;
            const int r = idx >> 3, c4 = idx & 7;
            const uint32_t so = SWZ((uint32_t)(r * 128 + c4 * 16));
            float4 h, l;
            h.x = tf32_hi(av[i].x); l.x = av[i].x - h.x;
            h.y = tf32_hi(av[i].y); l.y = av[i].y - h.y;
            h.z = tf32_hi(av[i].z); l.z = av[i].z - h.z;
            h.w = tf32_hi(av[i].w); l.w = av[i].w - h.w;
            *(float4*)(buf + OFF_AH + so) = h;
            *(float4*)(buf + OFF_AL + so) = l;
        }
#pragma unroll
        for (int i = 0; i < 8; i++) {
            const int idx = tid + 256 * i;
            const int r = idx >> 3, c4 = idx & 7;
            const uint32_t so = SWZ((uint32_t)(r * 128 + c4 * 16));
            float4 h, l;
            h.x = tf32_hi(bv[i].x); l.x = bv[i].x - h.x;
            h.y = tf32_hi(bv[i].y); l.y = bv[i].y - h.y;
            h.z = tf32_hi(bv[i].z); l.z = bv[i].z - h.z;
            h.w = tf32_hi(bv[i].w); l.w = bv[i].w - h.w;
            *(float4*)(buf + OFF_BH + so) = h;
            *(float4*)(buf + OFF_BL + so) = l;
        }
        fence_async_smem();
        __syncthreads();

        // ---- issue 12 MMAs (hh, hl, lh) ----
        if (tid < 32) {
            if (elect1()) {
                const uint64_t dAh = mkdesc(bufu + OFF_AH);
                const uint64_t dAl = mkdesc(bufu + OFF_AL);
                const uint64_t dBh = mkdesc(bufu + OFF_BH);
                const uint64_t dBl = mkdesc(bufu + OFF_BL);
#pragma unroll
                for (int ks = 0; ks < 4; ks++)
                    mma_tf32(tmem, dAh + 2 * ks, dBh + 2 * ks, IDESC_TF32,
                             (kt == 0 && ks == 0) ? 0u : 1u);
#pragma unroll
                for (int ks = 0; ks < 4; ks++)
                    mma_tf32(tmem, dAh + 2 * ks, dBl + 2 * ks, IDESC_TF32, 1u);
#pragma unroll
                for (int ks = 0; ks < 4; ks++)
                    mma_tf32(tmem, dAl + 2 * ks, dBh + 2 * ks, IDESC_TF32, 1u);
                tc_commit(sb + (bsel ? SM_MBAR1 : SM_MBAR0));
            }
        }
    }

    // drain both buffers' final commits
    mbar_wait(sb + SM_MBAR0, ph0 & 1);
    mbar_wait(sb + SM_MBAR1, ph1 & 1);
    tc_fence_after();

    // ---- epilogue: warps 0-3 read D from TMEM, add bias, store ----
    if (tid < 128) {
        const int m = row0 + tid;
        float* Crow = C + (size_t)m * HIDN + col0;
#pragma unroll
        for (int n0 = 0; n0 < GBN; n0 += 32) {
            uint32_t r[32];
            TC_LD_X32(r, tmem + n0);
            tc_wait_ld();
#pragma unroll
            for (int j = 0; j < 32; j += 4) {
                float4 o;
                o.x = __uint_as_float(r[j + 0]) + bias[col0 + n0 + j + 0];
                o.y = __uint_as_float(r[j + 1]) + bias[col0 + n0 + j + 1];
                o.z = __uint_as_float(r[j + 2]) + bias[col0 + n0 + j + 2];
                o.w = __uint_as_float(r[j + 3]) + bias[col0 + n0 + j + 3];
                *(float4*)(Crow + n0 + j) = o;
            }
        }
    }
    __syncthreads();
    if (tid < 32) tmem_dealloc(tmem, 256);
#endif  // HAS_TC  (stub body otherwise; host detects via numRegs)
}

// ===========================================================================
// Weight transpose: WT[n][k] = W[k][n], 4 matrices (z-dim selects).
// ===========================================================================
__global__ __launch_bounds__(256)
void transpose4(const float* __restrict__ s0, const float* __restrict__ s1,
                const float* __restrict__ s2, const float* __restrict__ s3,
                float* __restrict__ dst)
{
    __shared__ float t[32][33];
    const float* src = (blockIdx.z == 0) ? s0 : (blockIdx.z == 1) ? s1
                     : (blockIdx.z == 2) ? s2 : s3;
    float* d = dst + (size_t)blockIdx.z * HIDN * HIDN;
    const int x0 = blockIdx.x * 32, y0 = blockIdx.y * 32;
    const int tx = threadIdx.x & 31, ty0 = threadIdx.x >> 5;
#pragma unroll
    for (int i = 0; i < 4; i++) {
        const int ty = ty0 + i * 8;
        t[ty][tx] = src[(size_t)(y0 + ty) * HIDN + x0 + tx];
    }
    __syncthreads();
#pragma unroll
    for (int i = 0; i < 4; i++) {
        const int ty = ty0 + i * 8;
        d[(size_t)(x0 + ty) * HIDN + y0 + tx] = t[tx][ty];
    }
}

// ===========================================================================
// Fallback SGEMM (fp32, proven 3.75ms path) — compiles on every arch.
// ===========================================================================
#define BM 128
#define BN 128
#define BK 16

__global__ __launch_bounds__(256, 2)
void sgemm_bias(const float* __restrict__ A, const float* __restrict__ W,
                const float* __restrict__ bias, float* __restrict__ C,
                int M, int N, int K)
{
    __shared__ float As[2][BK][BM];
    __shared__ float Bs[2][BK][BN];

    const int tid = threadIdx.x;
    const int tx  = tid & 15;
    const int ty  = tid >> 4;
    const int row0 = blockIdx.y * BM;
    const int col0 = blockIdx.x * BN;

    const int a_r = tid >> 2;
    const int a_k = (tid & 3) << 2;
    const int b_r = tid >> 5;
    const int b_c = (tid & 31) << 2;

    const float* Ab = A + (size_t)row0 * K;

    float acc[8][8];
#pragma unroll
    for (int i = 0; i < 8; i++)
#pragma unroll
        for (int j = 0; j < 8; j++) acc[i][j] = 0.f;

    {
        float4 a0 = *(const float4*)(Ab + (size_t)a_r * K + a_k);
        float4 a1 = *(const float4*)(Ab + (size_t)(a_r + 64) * K + a_k);
        float4 w0 = *(const float4*)(W + (size_t)b_r * N + col0 + b_c);
        float4 w1 = *(const float4*)(W + (size_t)(b_r + 8) * N + col0 + b_c);
        As[0][a_k + 0][a_r] = a0.x; As[0][a_k + 1][a_r] = a0.y;
        As[0][a_k + 2][a_r] = a0.z; As[0][a_k + 3][a_r] = a0.w;
        As[0][a_k + 0][a_r + 64] = a1.x; As[0][a_k + 1][a_r + 64] = a1.y;
        As[0][a_k + 2][a_r + 64] = a1.z; As[0][a_k + 3][a_r + 64] = a1.w;
        *(float4*)&Bs[0][b_r][b_c]     = w0;
        *(float4*)&Bs[0][b_r + 8][b_c] = w1;
    }
    __syncthreads();

    const int NT = K / BK;
    for (int kt = 0; kt < NT; kt++) {
        const int cur = kt & 1;

        float4 a0, a1, w0, w1;
        const bool more = (kt + 1 < NT);
        if (more) {
            const float* Ap = Ab + (size_t)(kt + 1) * BK;
            a0 = *(const float4*)(Ap + (size_t)a_r * K + a_k);
            a1 = *(const float4*)(Ap + (size_t)(a_r + 64) * K + a_k);
            const float* Wp = W + (size_t)(kt + 1) * BK * N + col0;
            w0 = *(const float4*)(Wp + (size_t)b_r * N + b_c);
            w1 = *(const float4*)(Wp + (size_t)(b_r + 8) * N + b_c);
        }

#pragma unroll
        for (int kk = 0; kk < BK; kk++) {
            float ar[8], br[8];
            *(float4*)(ar)     = *(const float4*)&As[cur][kk][ty * 8];
            *(float4*)(ar + 4) = *(const float4*)&As[cur][kk][ty * 8 + 4];
            *(float4*)(br)     = *(const float4*)&Bs[cur][kk][tx * 8];
            *(float4*)(br + 4) = *(const float4*)&Bs[cur][kk][tx * 8 + 4];
#pragma unroll
            for (int i = 0; i < 8; i++)
#pragma unroll
                for (int j = 0; j < 8; j++)
                    acc[i][j] += ar[i] * br[j];
        }

        if (more) {
            const int nxt = cur ^ 1;
            As[nxt][a_k + 0][a_r] = a0.x; As[nxt][a_k + 1][a_r] = a0.y;
            As[nxt][a_k + 2][a_r] = a0.z; As[nxt][a_k + 3][a_r] = a0.w;
            As[nxt][a_k + 0][a_r + 64] = a1.x; As[nxt][a_k + 1][a_r + 64] = a1.y;
            As[nxt][a_k + 2][a_r + 64] = a1.z; As[nxt][a_k + 3][a_r + 64] = a1.w;
            *(float4*)&Bs[nxt][b_r][b_c]     = w0;
            *(float4*)&Bs[nxt][b_r + 8][b_c] = w1;
        }
        __syncthreads();
    }

#pragma unroll
    for (int i = 0; i < 8; i++) {
        const size_t r = (size_t)(row0 + ty * 8 + i);
#pragma unroll
        for (int j4 = 0; j4 < 8; j4 += 4) {
            const int c = col0 + tx * 8 + j4;
            float4 o;
            o.x = acc[i][j4 + 0] + bias[c + 0];
            o.y = acc[i][j4 + 1] + bias[c + 1];
            o.z = acc[i][j4 + 2] + bias[c + 2];
            o.w = acc[i][j4 + 3] + bias[c + 3];
            *(float4*)&C[r * N + c] = o;
        }
    }
}

// ===========================================================================
// Per-token attention over the HEADS axis.
// ===========================================================================
#define PD 68

__global__ __launch_bounds__(256)
void attn_kernel(const float* __restrict__ q, const float* __restrict__ k,
                 const float* __restrict__ v, const float* __restrict__ sw,
                 float* __restrict__ xperm, float* __restrict__ attn_out,
                 int write_attn)
{
    __shared__ float sq[NH][PD], sk[NH][PD], sv[NH][PD];
    __shared__ float s_qk[NH][NH];
    __shared__ float s_qn2[NH], s_kn2[NH];
    __shared__ float s_at[NH][NH + 1];

    const int t   = blockIdx.x;
    const int b   = t >> 12;
    const int s   = t & 4095;
    const int tid = threadIdx.x;
    const size_t base = (size_t)t * HIDN;

    {
        const int row = tid >> 4;
        const int col = (tid & 15) << 2;
        *(float4*)&sq[row][col] = *(const float4*)(q + base + row * HD + col);
        *(float4*)&sk[row][col] = *(const float4*)(k + base + row * HD + col);
        *(float4*)&sv[row][col] = *(const float4*)(v + base + row * HD + col);
    }
    __syncthreads();

    if (tid < 32) {
        const int i = tid & 15;
        const float* p = (tid < 16) ? sq[i] : sk[i];
        float ss = 0.f;
#pragma unroll
        for (int d = 0; d < HD; d++) ss += p[d] * p[d];
        if (tid < 16) s_qn2[i] = ss; else s_kn2[i] = ss;
    }
    {
        const int i = tid >> 4, j = tid & 15;
        float dot = 0.f;
#pragma unroll
        for (int d = 0; d < HD; d++) dot += sq[i][d] * sk[j][d];
        s_qk[i][j] = dot;
    }
    __syncthreads();

    if (tid < NH) {
        float w0, w1, w2;
        {
            const float x0 = sw[0], x1 = sw[1], x2 = sw[2];
            const float m  = fmaxf(x0, fmaxf(x1, x2));
            const float e0 = expf(x0 - m), e1 = expf(x1 - m), e2 = expf(x2 - m);
            const float inv = 1.f / (e0 + e1 + e2);
            w0 = e0 * inv; w1 = e1 * inv; w2 = e2 * inv;
        }
        const int i = tid;
        const float qn2 = s_qn2[i];
        const float qn  = sqrtf(qn2);
        float sc[NH];
        float mx = -1e30f;
#pragma unroll
        for (int j = 0; j < NH; j++) {
            const float qkv  = s_qk[i][j];
            const float kn2  = s_kn2[j];
            const float dotv = qkv * 0.125f;
            const float cosv = qkv / fmaxf(qn * sqrtf(kn2), 1e-8f);
            const float d2   = fmaxf(qn2 + kn2 - 2.f * qkv, 0.f);
            const float dstv = -sqrtf(d2);
            const float scv  = w0 * dotv + w1 * cosv + w2 * dstv;
            sc[j] = scv;
            mx = fmaxf(mx, scv);
        }
        float ssum = 0.f;
#pragma unroll
        for (int j = 0; j < NH; j++) { const float e = expf(sc[j] - mx); sc[j] = e; ssum += e; }
        const float inv = 1.f / ssum;
#pragma unroll
        for (int j = 0; j < NH; j++) {
            const float a = sc[j] * inv;
            s_at[i][j] = a;
            if (write_attn)
                attn_out[(size_t)t * (NH * NH) + i * NH + j] = a;
        }
    }
    __syncthreads();

    {
        const int i  = tid >> 4;
        const int db = (tid & 15) << 2;
        float4 o = make_float4(0.f, 0.f, 0.f, 0.f);
#pragma unroll
        for (int j = 0; j < NH; j++) {
            const float a = s_at[i][j];
            const float4 vv = *(const float4*)&sv[j][db];
            o.x += a * vv.x; o.y += a * vv.y; o.z += a * vv.z; o.w += a * vv.w;
        }
        const size_t dst = (size_t)b * ((size_t)SEQ * HIDN)
                         + (size_t)((i << 8) + (s >> 4)) * HIDN
                         + (size_t)((s & 15) << 6) + db;
        *(float4*)&xperm[dst] = o;
    }
}

// ===========================================================================
extern "C" void kernel_launch(void* const* d_in, const int* in_sizes, int n_in,
                              void* d_out, int out_size)
{
    const float* query = (const float*)d_in[0];
    const float* key_  = (const float*)d_in[1];
    const float* value = (const float*)d_in[2];
    const float* Wq    = (const float*)d_in[3];
    const float* bq    = (const float*)d_in[4];
    const float* Wk    = (const float*)d_in[5];
    const float* bk    = (const float*)d_in[6];
    const float* Wv    = (const float*)d_in[7];
    const float* bv    = (const float*)d_in[8];
    const float* Wo    = (const float*)d_in[9];
    const float* bo    = (const float*)d_in[10];
    const float* sw    = (const float*)d_in[11];
    float* out = (float*)d_out;

    float *gq, *gk, *gv, *gx, *gwt;
    cudaGetSymbolAddress((void**)&gq,  g_q);
    cudaGetSymbolAddress((void**)&gk,  g_k);
    cudaGetSymbolAddress((void**)&gv,  g_v);
    cudaGetSymbolAddress((void**)&gx,  g_x);
    cudaGetSymbolAddress((void**)&gwt, g_wt);

    const long long main_elems = (long long)MTOT * HIDN;
    const long long attn_elems = (long long)MTOT * NH * NH;
    const int write_attn = ((long long)out_size >= main_elems + attn_elems) ? 1 : 0;
    float* attn_ptr = out + main_elems;

    // Detect whether the tcgen05 path was compiled into the loaded cubin:
    // the stubbed (non-'a' pass) kernel uses only a handful of registers.
    cudaFuncAttributes fa;
    fa.numRegs = 0;
    cudaError_t perr = cudaFuncGetAttributes(&fa, gemm_tf32x3);
    const bool use_tc = (perr == cudaSuccess) && (fa.numRegs >= 40);

    if (use_tc) {
        cudaFuncSetAttribute(gemm_tf32x3, cudaFuncAttributeMaxDynamicSharedMemorySize,
                             GEMM_SMEM_BYTES);

        // Transpose all 4 weight matrices: [K,N] -> [N,K]
        transpose4<<<dim3(32, 32, 4), 256>>>(Wq, Wk, Wv, Wo, gwt);

        const size_t WSZ = (size_t)HIDN * HIDN;
        dim3 gg(HIDN / GBN, MTOT / GBM);   // (4, 128)

        gemm_tf32x3<<<gg, 256, GEMM_SMEM_BYTES>>>(query, gwt + 0 * WSZ, bq, gq);
        gemm_tf32x3<<<gg, 256, GEMM_SMEM_BYTES>>>(key_,  gwt + 1 * WSZ, bk, gk);
        gemm_tf32x3<<<gg, 256, GEMM_SMEM_BYTES>>>(value, gwt + 2 * WSZ, bv, gv);

        attn_kernel<<<MTOT, 256>>>(gq, gk, gv, sw, gx, attn_ptr, write_attn);

        gemm_tf32x3<<<gg, 256, GEMM_SMEM_BYTES>>>(gx, gwt + 3 * WSZ, bo, out);
    } else {
        // Fallback: proven fp32 path.
        dim3 gg(HIDN / BN, MTOT / BM);
        sgemm_bias<<<gg, 256>>>(query, Wq, bq, gq, MTOT, HIDN, HIDN);
        sgemm_bias<<<gg, 256>>>(key_,  Wk, bk, gk, MTOT, HIDN, HIDN);
        sgemm_bias<<<gg, 256>>>(value, Wv, bv, gv, MTOT, HIDN, HIDN);

        attn_kernel<<<MTOT, 256>>>(gq, gk, gv, sw, gx, attn_ptr, write_attn);

        sgemm_bias<<<gg, 256>>>(gx, Wo, bo, out, MTOT, HIDN, HIDN);
    }
}

// round 6
// speedup vs baseline: 5.4693x; 1.5908x over previous
#include <cuda_runtime.h>
#include <cuda_bf16.h>
#include <cstdint>

// Problem constants
#define B_SZ  4
#define SEQ   4096
#define HIDN  1024
#define NH    16
#define HD    64
#define MTOT  (B_SZ * SEQ)   // 16384 tokens

// Arch-feature gate: tcgen05/TMEM only legal in arch-specific ('a') passes.
#if defined(__CUDA_ARCH__) && (defined(__CUDA_ARCH_FEAT_SM103_ALL) || defined(__CUDA_ARCH_FEAT_SM100_ALL) || defined(__CUDA_ARCH_FEAT_SM101_ALL))
#define HAS_TC 1
#else
#define HAS_TC 0
#endif

// Scratch (device globals: no allocations allowed in kernel_launch)
static __device__ float g_q[(size_t)MTOT * HIDN];
static __device__ float g_k[(size_t)MTOT * HIDN];
static __device__ float g_v[(size_t)MTOT * HIDN];
static __device__ float g_x[(size_t)MTOT * HIDN];
static __device__ __nv_bfloat16 g_wbh[(size_t)4 * HIDN * HIDN];  // weights^T hi, [4][N][K]
static __device__ __nv_bfloat16 g_wbl[(size_t)4 * HIDN * HIDN];  // weights^T lo

// ===========================================================================
// GEMM tile geometry (tensor path): 128x256 tile, BK=64 (bf16 -> 128B rows)
// ===========================================================================
#define GBM 128
#define GBN 256
#define GBK 64
#define GKD 1024
#define GNCH (GKD / GBK)          // 16 stages

#define SM_TMEM   0
#define SM_MBAR0  8
#define SM_MBAR1  16
#define SM_BUF    1024
#define BUF_STRIDE 98304          // 96 KB per stage
#define OFF_AH 0                  // 16 KB  (128 x 64 bf16)
#define OFF_AL 16384              // 16 KB
#define OFF_BH 32768              // 32 KB  (256 x 64 bf16)
#define OFF_BL 65536              // 32 KB
#define GEMM_SMEM_BYTES (1024 + 2 * BUF_STRIDE)   // 197632

// idesc: dtype=F32(1)<<4 | atype=BF16(1)<<7 | btype=BF16(1)<<10 | (N/8)<<17 | (M/16)<<24
#define IDESC_BF16 ((1u << 4) | (1u << 7) | (1u << 10) | ((GBN / 8) << 17) | ((GBM / 16) << 24))

extern __shared__ char dynsmem[];

#if HAS_TC
// ---------------------------------------------------------------------------
// tcgen05 helpers (arch-specific pass only)
// ---------------------------------------------------------------------------
__device__ __forceinline__ uint32_t s2u(const void* p) {
    uint32_t a;
    asm("{ .reg .u64 t; cvta.to.shared.u64 t, %1; cvt.u32.u64 %0, t; }"
        : "=r"(a) : "l"(p));
    return a;
}
__device__ __forceinline__ uint64_t to_global(const void* p) {
    uint64_t g;
    asm("cvta.to.global.u64 %0, %1;" : "=l"(g) : "l"(p));
    return g;
}
__device__ __forceinline__ bool elect1() {
    uint32_t p;
    asm volatile("{ .reg .pred p; elect.sync _|p, 0xFFFFFFFF; selp.b32 %0, 1, 0, p; }"
                 : "=r"(p));
    return p != 0;
}
__device__ __forceinline__ void mbar_init(uint32_t mbar, uint32_t cnt) {
    asm volatile("mbarrier.init.shared.b64 [%0], %1;" :: "r"(mbar), "r"(cnt) : "memory");
}
__device__ __forceinline__ void mbar_wait(uint32_t mbar, uint32_t parity) {
    asm volatile(
        "{\n\t"
        ".reg .pred P;\n\t"
        "WL%=:\n\t"
        "mbarrier.try_wait.parity.acquire.cta.shared::cta.b64 P, [%0], %1, 0x989680;\n\t"
        "@P bra.uni WD%=;\n\t"
        "bra.uni WL%=;\n\t"
        "WD%=:\n\t"
        "}"
        :: "r"(mbar), "r"(parity) : "memory");
}
__device__ __forceinline__ void tmem_alloc(uint32_t smem_dst, uint32_t ncols) {
    asm volatile("tcgen05.alloc.cta_group::1.sync.aligned.shared::cta.b32 [%0], %1;"
                 :: "r"(smem_dst), "r"(ncols) : "memory");
}
__device__ __forceinline__ void tmem_relinquish() {
    asm volatile("tcgen05.relinquish_alloc_permit.cta_group::1.sync.aligned;");
}
__device__ __forceinline__ void tmem_dealloc(uint32_t tmem, uint32_t ncols) {
    asm volatile("tcgen05.dealloc.cta_group::1.sync.aligned.b32 %0, %1;"
                 :: "r"(tmem), "r"(ncols));
}
__device__ __forceinline__ void tc_commit(uint32_t mbar) {
    asm volatile("tcgen05.commit.cta_group::1.mbarrier::arrive::one.shared::cluster.b64 [%0];"
                 :: "r"(mbar) : "memory");
}
__device__ __forceinline__ void tc_fence_after() {
    asm volatile("tcgen05.fence::after_thread_sync;" ::: "memory");
}
__device__ __forceinline__ void fence_async_smem() {
    asm volatile("fence.proxy.async.shared::cta;" ::: "memory");
}
__device__ __forceinline__ void tc_wait_ld() {
    asm volatile("tcgen05.wait::ld.sync.aligned;" ::: "memory");
}
__device__ __forceinline__ void cp16(uint32_t dst_smem, uint64_t src_gmem) {
    asm volatile("cp.async.cg.shared.global [%0], [%1], 16;"
                 :: "r"(dst_smem), "l"(src_gmem) : "memory");
}
__device__ __forceinline__ void cp_wait_all() {
    asm volatile("cp.async.wait_all;" ::: "memory");
}

// SS bf16 MMA, cta_group::1 (kind::f16 with bf16 idesc bits)
__device__ __forceinline__ void mma_bf16(uint32_t d_tmem, uint64_t a_desc,
                                         uint64_t b_desc, uint32_t idesc, uint32_t en) {
    asm volatile(
        "{\n\t"
        ".reg .pred p;\n\t"
        "setp.ne.u32 p, %4, 0;\n\t"
        "tcgen05.mma.cta_group::1.kind::f16 [%0], %1, %2, %3, {%5, %5, %5, %5}, p;\n\t"
        "}"
        :: "r"(d_tmem), "l"(a_desc), "l"(b_desc), "r"(idesc), "r"(en), "r"(0u)
        : "memory");
}

#define TC_LD_X32(r, addr)                                                     \
    asm volatile(                                                              \
        "tcgen05.ld.sync.aligned.32x32b.x32.b32 "                              \
        "{%0, %1, %2, %3, %4, %5, %6, %7, "                                    \
        " %8, %9, %10, %11, %12, %13, %14, %15, "                              \
        " %16, %17, %18, %19, %20, %21, %22, %23, "                            \
        " %24, %25, %26, %27, %28, %29, %30, %31}, [%32];"                     \
        : "=r"((r)[0]),  "=r"((r)[1]),  "=r"((r)[2]),  "=r"((r)[3]),           \
          "=r"((r)[4]),  "=r"((r)[5]),  "=r"((r)[6]),  "=r"((r)[7]),           \
          "=r"((r)[8]),  "=r"((r)[9]),  "=r"((r)[10]), "=r"((r)[11]),          \
          "=r"((r)[12]), "=r"((r)[13]), "=r"((r)[14]), "=r"((r)[15]),          \
          "=r"((r)[16]), "=r"((r)[17]), "=r"((r)[18]), "=r"((r)[19]),          \
          "=r"((r)[20]), "=r"((r)[21]), "=r"((r)[22]), "=r"((r)[23]),          \
          "=r"((r)[24]), "=r"((r)[25]), "=r"((r)[26]), "=r"((r)[27]),          \
          "=r"((r)[28]), "=r"((r)[29]), "=r"((r)[30]), "=r"((r)[31])           \
        : "r"(addr))

#define SWZ(o) ((o) ^ (((o) >> 3) & 0x70))

// SW128 descriptor: layout=2<<61 | version=1<<46 | SBO=64<<32 | LBO=1<<16
__device__ __forceinline__ uint64_t mkdesc(uint32_t smem_addr) {
    return 0x4000404000010000ull | ((uint64_t)(smem_addr >> 4) & 0x3FFF);
}

// ---------------------------------------------------------------------------
// GEMM core: C[128,256 tile] = A @ Wh^T (x3 split) + bias
// A fp32 [M,K]; Wh/Wl bf16 [N,K] pre-split.
// ---------------------------------------------------------------------------
__device__ __forceinline__ void gemm_core(const float* __restrict__ A,
                                          const __nv_bfloat16* __restrict__ Wh,
                                          const __nv_bfloat16* __restrict__ Wl,
                                          const float* __restrict__ bias,
                                          float* __restrict__ C)
{
    char* sm = dynsmem;
    const uint32_t sb = s2u(dynsmem);
    const int tid  = threadIdx.x;
    const int row0 = blockIdx.y * GBM;
    const int col0 = blockIdx.x * GBN;

    if (tid < 32) {
        tmem_alloc(sb + SM_TMEM, 256);
        tmem_relinquish();
    }
    if (tid == 0) {
        mbar_init(sb + SM_MBAR0, 1);
        mbar_init(sb + SM_MBAR1, 1);
    }
    __syncthreads();

    uint32_t tmem;
    asm volatile("ld.shared.b32 %0, [%1];" : "=r"(tmem) : "r"(sb + SM_TMEM));

    // A mapping: thread covers row ar, 32 consecutive k at offset ako
    const int ar  = tid >> 1;
    const int ako = (tid & 1) * 32;
    const float* aptr = A + (size_t)(row0 + ar) * GKD + ako;

    // B mapping (cp.async 16B granules): 2048 granules per half per stage
    const uint64_t whg = to_global(Wh);
    const uint64_t wlg = to_global(Wl);

    // Prefetch A regs for stage 0
    float4 areg[8];
#pragma unroll
    for (int i = 0; i < 8; i++) areg[i] = *(const float4*)(aptr + i * 4);

    int ph0 = 0, ph1 = 0;

    for (int kt = 0; kt < GNCH; kt++) {
        const int bsel = kt & 1;
        char* buf = sm + SM_BUF + bsel * BUF_STRIDE;
        const uint32_t bufu = sb + SM_BUF + bsel * BUF_STRIDE;

        // wait for MMA batch that last read this stage's buffers
        if (kt >= 2) {
            if (bsel == 0) { mbar_wait(sb + SM_MBAR0, ph0 & 1); ph0++; }
            else           { mbar_wait(sb + SM_MBAR1, ph1 & 1); ph1++; }
        }

        // ---- B: cp.async pre-split bf16 weights into SW128 smem ----
#pragma unroll
        for (int j = 0; j < 8; j++) {
            const int c  = tid + 256 * j;
            const int n  = c >> 3;
            const int k8 = c & 7;
            const uint64_t sboff = ((uint64_t)(col0 + n) * GKD + kt * GBK + k8 * 8) * 2;
            const uint32_t doff  = SWZ((uint32_t)(n * 128 + k8 * 16));
            cp16(bufu + OFF_BH + doff, whg + sboff);
            cp16(bufu + OFF_BL + doff, wlg + sboff);
        }

        // ---- A: split fp32 -> bf16 hi/lo, swizzled STS ----
        {
            const float* af = (const float*)areg;
            uint32_t hiw[16], low[16];
#pragma unroll
            for (int i = 0; i < 16; i++) {
                const float x0 = af[2 * i], x1 = af[2 * i + 1];
                __nv_bfloat162 h2 = __floats2bfloat162_rn(x0, x1);
                const float2 hf = __bfloat1622float2(h2);
                __nv_bfloat162 l2 = __floats2bfloat162_rn(x0 - hf.x, x1 - hf.y);
                hiw[i] = *(uint32_t*)&h2;
                low[i] = *(uint32_t*)&l2;
            }
            const uint32_t rb = (uint32_t)(ar * 128 + ako * 2);
#pragma unroll
            for (int i = 0; i < 4; i++) {
                const uint32_t so = SWZ(rb + i * 16);
                *(uint4*)(buf + OFF_AH + so) = *(uint4*)&hiw[i * 4];
                *(uint4*)(buf + OFF_AL + so) = *(uint4*)&low[i * 4];
            }
        }

        // ---- prefetch next stage's A into regs (flies under this MMA) ----
        if (kt + 1 < GNCH) {
            const float* ap = aptr + (kt + 1) * GBK;
#pragma unroll
            for (int i = 0; i < 8; i++) areg[i] = *(const float4*)(ap + i * 4);
        }

        cp_wait_all();
        fence_async_smem();
        __syncthreads();

        // ---- issue 12 MMAs (hh, hl, lh) x 4 ksteps ----
        if (tid < 32) {
            if (elect1()) {
                const uint64_t dAh = mkdesc(bufu + OFF_AH);
                const uint64_t dAl = mkdesc(bufu + OFF_AL);
                const uint64_t dBh = mkdesc(bufu + OFF_BH);
                const uint64_t dBl = mkdesc(bufu + OFF_BL);
#pragma unroll
                for (int ks = 0; ks < 4; ks++)
                    mma_bf16(tmem, dAh + 2 * ks, dBh + 2 * ks, IDESC_BF16,
                             (kt == 0 && ks == 0) ? 0u : 1u);
#pragma unroll
                for (int ks = 0; ks < 4; ks++)
                    mma_bf16(tmem, dAh + 2 * ks, dBl + 2 * ks, IDESC_BF16, 1u);
#pragma unroll
                for (int ks = 0; ks < 4; ks++)
                    mma_bf16(tmem, dAl + 2 * ks, dBh + 2 * ks, IDESC_BF16, 1u);
                tc_commit(sb + (bsel ? SM_MBAR1 : SM_MBAR0));
            }
        }
    }

    // drain both stage slots' final commits
    mbar_wait(sb + SM_MBAR0, ph0 & 1);
    mbar_wait(sb + SM_MBAR1, ph1 & 1);
    tc_fence_after();

    // ---- epilogue: warps 0-3 read D from TMEM, add bias, store ----
    if (tid < 128) {
        const int m = row0 + tid;
        float* Crow = C + (size_t)m * HIDN + col0;
#pragma unroll
        for (int n0 = 0; n0 < GBN; n0 += 32) {
            uint32_t r[32];
            TC_LD_X32(r, tmem + n0);
            tc_wait_ld();
#pragma unroll
            for (int j = 0; j < 32; j += 4) {
                float4 o;
                o.x = __uint_as_float(r[j + 0]) + bias[col0 + n0 + j + 0];
                o.y = __uint_as_float(r[j + 1]) + bias[col0 + n0 + j + 1];
                o.z = __uint_as_float(r[j + 2]) + bias[col0 + n0 + j + 2];
                o.w = __uint_as_float(r[j + 3]) + bias[col0 + n0 + j + 3];
                *(float4*)(Crow + n0 + j) = o;
            }
        }
    }
    __syncthreads();
    if (tid < 32) tmem_dealloc(tmem, 256);
}
#endif  // HAS_TC

// Merged QKV GEMM (z selects input/weight/bias/output) — better wave balance.
__global__ __launch_bounds__(256, 1)
void gemm_qkv(const float* __restrict__ q_in, const float* __restrict__ k_in,
              const float* __restrict__ v_in,
              const __nv_bfloat16* __restrict__ wh, const __nv_bfloat16* __restrict__ wl,
              const float* __restrict__ bq, const float* __restrict__ bk,
              const float* __restrict__ bv,
              float* __restrict__ oq, float* __restrict__ ok, float* __restrict__ ov)
{
#if HAS_TC
    const int z = blockIdx.z;
    const float* A = (z == 0) ? q_in : (z == 1) ? k_in : v_in;
    const float* bias = (z == 0) ? bq : (z == 1) ? bk : bv;
    float* C = (z == 0) ? oq : (z == 1) ? ok : ov;
    const size_t wo = (size_t)z * HIDN * HIDN;
    gemm_core(A, wh + wo, wl + wo, bias, C);
#endif
}

// Single GEMM (used for output projection; also the runtime capability probe).
__global__ __launch_bounds__(256, 1)
void gemm_single(const float* __restrict__ A,
                 const __nv_bfloat16* __restrict__ wh, const __nv_bfloat16* __restrict__ wl,
                 const float* __restrict__ bias, float* __restrict__ C)
{
#if HAS_TC
    gemm_core(A, wh, wl, bias, C);
#endif
}

// ===========================================================================
// Weight prep: WTh[n][k] = bf16(W[k][n]), WTl = bf16(residual). 4 matrices.
// ===========================================================================
__global__ __launch_bounds__(256)
void prep_weights(const float* __restrict__ s0, const float* __restrict__ s1,
                  const float* __restrict__ s2, const float* __restrict__ s3,
                  __nv_bfloat16* __restrict__ dh, __nv_bfloat16* __restrict__ dl)
{
    __shared__ float t[32][33];
    const float* src = (blockIdx.z == 0) ? s0 : (blockIdx.z == 1) ? s1
                     : (blockIdx.z == 2) ? s2 : s3;
    const size_t zo = (size_t)blockIdx.z * HIDN * HIDN;
    const int x0 = blockIdx.x * 32, y0 = blockIdx.y * 32;   // x: n, y: k
    const int tx = threadIdx.x & 31, ty0 = threadIdx.x >> 5;
#pragma unroll
    for (int i = 0; i < 4; i++) {
        const int ty = ty0 + i * 8;
        t[ty][tx] = src[(size_t)(y0 + ty) * HIDN + x0 + tx];
    }
    __syncthreads();
#pragma unroll
    for (int i = 0; i < 4; i++) {
        const int ty = ty0 + i * 8;
        const float val = t[tx][ty];
        const __nv_bfloat16 h = __float2bfloat16_rn(val);
        const __nv_bfloat16 l = __float2bfloat16_rn(val - __bfloat162float(h));
        const size_t di = zo + (size_t)(x0 + ty) * HIDN + (y0 + tx);
        dh[di] = h;
        dl[di] = l;
    }
}

// ===========================================================================
// Fallback SGEMM (fp32, proven path) — compiles on every arch.
// ===========================================================================
#define BM 128
#define BN 128
#define BK 16

__global__ __launch_bounds__(256, 2)
void sgemm_bias(const float* __restrict__ A, const float* __restrict__ W,
                const float* __restrict__ bias, float* __restrict__ C,
                int M, int N, int K)
{
    __shared__ float As[2][BK][BM];
    __shared__ float Bs[2][BK][BN];

    const int tid = threadIdx.x;
    const int tx  = tid & 15;
    const int ty  = tid >> 4;
    const int row0 = blockIdx.y * BM;
    const int col0 = blockIdx.x * BN;

    const int a_r = tid >> 2;
    const int a_k = (tid & 3) << 2;
    const int b_r = tid >> 5;
    const int b_c = (tid & 31) << 2;

    const float* Ab = A + (size_t)row0 * K;

    float acc[8][8];
#pragma unroll
    for (int i = 0; i < 8; i++)
#pragma unroll
        for (int j = 0; j < 8; j++) acc[i][j] = 0.f;

    {
        float4 a0 = *(const float4*)(Ab + (size_t)a_r * K + a_k);
        float4 a1 = *(const float4*)(Ab + (size_t)(a_r + 64) * K + a_k);
        float4 w0 = *(const float4*)(W + (size_t)b_r * N + col0 + b_c);
        float4 w1 = *(const float4*)(W + (size_t)(b_r + 8) * N + col0 + b_c);
        As[0][a_k + 0][a_r] = a0.x; As[0][a_k + 1][a_r] = a0.y;
        As[0][a_k + 2][a_r] = a0.z; As[0][a_k + 3][a_r] = a0.w;
        As[0][a_k + 0][a_r + 64] = a1.x; As[0][a_k + 1][a_r + 64] = a1.y;
        As[0][a_k + 2][a_r + 64] = a1.z; As[0][a_k + 3][a_r + 64] = a1.w;
        *(float4*)&Bs[0][b_r][b_c]     = w0;
        *(float4*)&Bs[0][b_r + 8][b_c] = w1;
    }
    __syncthreads();

    const int NT = K / BK;
    for (int kt = 0; kt < NT; kt++) {
        const int cur = kt & 1;

        float4 a0, a1, w0, w1;
        const bool more = (kt + 1 < NT);
        if (more) {
            const float* Ap = Ab + (size_t)(kt + 1) * BK;
            a0 = *(const float4*)(Ap + (size_t)a_r * K + a_k);
            a1 = *(const float4*)(Ap + (size_t)(a_r + 64) * K + a_k);
            const float* Wp = W + (size_t)(kt + 1) * BK * N + col0;
            w0 = *(const float4*)(Wp + (size_t)b_r * N + b_c);
            w1 = *(const float4*)(Wp + (size_t)(b_r + 8) * N + b_c);
        }

#pragma unroll
        for (int kk = 0; kk < BK; kk++) {
            float ar[8], br[8];
            *(float4*)(ar)     = *(const float4*)&As[cur][kk][ty * 8];
            *(float4*)(ar + 4) = *(const float4*)&As[cur][kk][ty * 8 + 4];
            *(float4*)(br)     = *(const float4*)&Bs[cur][kk][tx * 8];
            *(float4*)(br + 4) = *(const float4*)&Bs[cur][kk][tx * 8 + 4];
#pragma unroll
            for (int i = 0; i < 8; i++)
#pragma unroll
                for (int j = 0; j < 8; j++)
                    acc[i][j] += ar[i] * br[j];
        }

        if (more) {
            const int nxt = cur ^ 1;
            As[nxt][a_k + 0][a_r] = a0.x; As[nxt][a_k + 1][a_r] = a0.y;
            As[nxt][a_k + 2][a_r] = a0.z; As[nxt][a_k + 3][a_r] = a0.w;
            As[nxt][a_k + 0][a_r + 64] = a1.x; As[nxt][a_k + 1][a_r + 64] = a1.y;
            As[nxt][a_k + 2][a_r + 64] = a1.z; As[nxt][a_k + 3][a_r + 64] = a1.w;
            *(float4*)&Bs[nxt][b_r][b_c]     = w0;
            *(float4*)&Bs[nxt][b_r + 8][b_c] = w1;
        }
        __syncthreads();
    }

#pragma unroll
    for (int i = 0; i < 8; i++) {
        const size_t r = (size_t)(row0 + ty * 8 + i);
#pragma unroll
        for (int j4 = 0; j4 < 8; j4 += 4) {
            const int c = col0 + tx * 8 + j4;
            float4 o;
            o.x = acc[i][j4 + 0] + bias[c + 0];
            o.y = acc[i][j4 + 1] + bias[c + 1];
            o.z = acc[i][j4 + 2] + bias[c + 2];
            o.w = acc[i][j4 + 3] + bias[c + 3];
            *(float4*)&C[r * N + c] = o;
        }
    }
}

// ===========================================================================
// Per-token attention over the HEADS axis.
// ===========================================================================
#define PD 68

__global__ __launch_bounds__(256)
void attn_kernel(const float* __restrict__ q, const float* __restrict__ k,
                 const float* __restrict__ v, const float* __restrict__ sw,
                 float* __restrict__ xperm, float* __restrict__ attn_out,
                 int write_attn)
{
    __shared__ float sq[NH][PD], sk[NH][PD], sv[NH][PD];
    __shared__ float s_qk[NH][NH];
    __shared__ float s_qn2[NH], s_kn2[NH];
    __shared__ float s_at[NH][NH + 1];

    const int t   = blockIdx.x;
    const int b   = t >> 12;
    const int s   = t & 4095;
    const int tid = threadIdx.x;
    const size_t base = (size_t)t * HIDN;

    {
        const int row = tid >> 4;
        const int col = (tid & 15) << 2;
        *(float4*)&sq[row][col] = *(const float4*)(q + base + row * HD + col);
        *(float4*)&sk[row][col] = *(const float4*)(k + base + row * HD + col);
        *(float4*)&sv[row][col] = *(const float4*)(v + base + row * HD + col);
    }
    __syncthreads();

    if (tid < 32) {
        const int i = tid & 15;
        const float* p = (tid < 16) ? sq[i] : sk[i];
        float ss = 0.f;
#pragma unroll
        for (int d = 0; d < HD; d++) ss += p[d] * p[d];
        if (tid < 16) s_qn2[i] = ss; else s_kn2[i] = ss;
    }
    {
        const int i = tid >> 4, j = tid & 15;
        float dot = 0.f;
#pragma unroll
        for (int d = 0; d < HD; d++) dot += sq[i][d] * sk[j][d];
        s_qk[i][j] = dot;
    }
    __syncthreads();

    if (tid < NH) {
        float w0, w1, w2;
        {
            const float x0 = sw[0], x1 = sw[1], x2 = sw[2];
            const float m  = fmaxf(x0, fmaxf(x1, x2));
            const float e0 = expf(x0 - m), e1 = expf(x1 - m), e2 = expf(x2 - m);
            const float inv = 1.f / (e0 + e1 + e2);
            w0 = e0 * inv; w1 = e1 * inv; w2 = e2 * inv;
        }
        const int i = tid;
        const float qn2 = s_qn2[i];
        const float qn  = sqrtf(qn2);
        float sc[NH];
        float mx = -1e30f;
#pragma unroll
        for (int j = 0; j < NH; j++) {
            const float qkv  = s_qk[i][j];
            const float kn2  = s_kn2[j];
            const float dotv = qkv * 0.125f;
            const float cosv = qkv / fmaxf(qn * sqrtf(kn2), 1e-8f);
            const float d2   = fmaxf(qn2 + kn2 - 2.f * qkv, 0.f);
            const float dstv = -sqrtf(d2);
            const float scv  = w0 * dotv + w1 * cosv + w2 * dstv;
            sc[j] = scv;
            mx = fmaxf(mx, scv);
        }
        float ssum = 0.f;
#pragma unroll
        for (int j = 0; j < NH; j++) { const float e = expf(sc[j] - mx); sc[j] = e; ssum += e; }
        const float inv = 1.f / ssum;
#pragma unroll
        for (int j = 0; j < NH; j++) {
            const float a = sc[j] * inv;
            s_at[i][j] = a;
            if (write_attn)
                attn_out[(size_t)t * (NH * NH) + i * NH + j] = a;
        }
    }
    __syncthreads();

    {
        const int i  = tid >> 4;
        const int db = (tid & 15) << 2;
        float4 o = make_float4(0.f, 0.f, 0.f, 0.f);
#pragma unroll
        for (int j = 0; j < NH; j++) {
            const float a = s_at[i][j];
            const float4 vv = *(const float4*)&sv[j][db];
            o.x += a * vv.x; o.y += a * vv.y; o.z += a * vv.z; o.w += a * vv.w;
        }
        const size_t dst = (size_t)b * ((size_t)SEQ * HIDN)
                         + (size_t)((i << 8) + (s >> 4)) * HIDN
                         + (size_t)((s & 15) << 6) + db;
        *(float4*)&xperm[dst] = o;
    }
}

// ===========================================================================
extern "C" void kernel_launch(void* const* d_in, const int* in_sizes, int n_in,
                              void* d_out, int out_size)
{
    const float* query = (const float*)d_in[0];
    const float* key_  = (const float*)d_in[1];
    const float* value = (const float*)d_in[2];
    const float* Wq    = (const float*)d_in[3];
    const float* bq    = (const float*)d_in[4];
    const float* Wk    = (const float*)d_in[5];
    const float* bk    = (const float*)d_in[6];
    const float* Wv    = (const float*)d_in[7];
    const float* bv    = (const float*)d_in[8];
    const float* Wo    = (const float*)d_in[9];
    const float* bo    = (const float*)d_in[10];
    const float* sw    = (const float*)d_in[11];
    float* out = (float*)d_out;

    float *gq, *gk, *gv, *gx;
    __nv_bfloat16 *gwh, *gwl;
    cudaGetSymbolAddress((void**)&gq,  g_q);
    cudaGetSymbolAddress((void**)&gk,  g_k);
    cudaGetSymbolAddress((void**)&gv,  g_v);
    cudaGetSymbolAddress((void**)&gx,  g_x);
    cudaGetSymbolAddress((void**)&gwh, g_wbh);
    cudaGetSymbolAddress((void**)&gwl, g_wbl);

    const long long main_elems = (long long)MTOT * HIDN;
    const long long attn_elems = (long long)MTOT * NH * NH;
    const int write_attn = ((long long)out_size >= main_elems + attn_elems) ? 1 : 0;
    float* attn_ptr = out + main_elems;

    // Capability probe: stubbed (non-'a' pass) kernel uses only a few regs.
    cudaFuncAttributes fa;
    fa.numRegs = 0;
    cudaError_t perr = cudaFuncGetAttributes(&fa, gemm_single);
    const bool use_tc = (perr == cudaSuccess) && (fa.numRegs >= 40);

    if (use_tc) {
        cudaFuncSetAttribute(gemm_qkv, cudaFuncAttributeMaxDynamicSharedMemorySize,
                             GEMM_SMEM_BYTES);
        cudaFuncSetAttribute(gemm_single, cudaFuncAttributeMaxDynamicSharedMemorySize,
                             GEMM_SMEM_BYTES);

        // Transpose + bf16-split all 4 weight matrices
        prep_weights<<<dim3(32, 32, 4), 256>>>(Wq, Wk, Wv, Wo, gwh, gwl);

        const size_t WSZ = (size_t)HIDN * HIDN;
        dim3 gq3(HIDN / GBN, MTOT / GBM, 3);   // (4, 128, 3)
        dim3 gg1(HIDN / GBN, MTOT / GBM);

        gemm_qkv<<<gq3, 256, GEMM_SMEM_BYTES>>>(query, key_, value, gwh, gwl,
                                                bq, bk, bv, gq, gk, gv);

        attn_kernel<<<MTOT, 256>>>(gq, gk, gv, sw, gx, attn_ptr, write_attn);

        gemm_single<<<gg1, 256, GEMM_SMEM_BYTES>>>(gx, gwh + 3 * WSZ, gwl + 3 * WSZ,
                                                   bo, out);
    } else {
        // Fallback: proven fp32 path.
        dim3 gg(HIDN / BN, MTOT / BM);
        sgemm_bias<<<gg, 256>>>(query, Wq, bq, gq, MTOT, HIDN, HIDN);
        sgemm_bias<<<gg, 256>>>(key_,  Wk, bk, gk, MTOT, HIDN, HIDN);
        sgemm_bias<<<gg, 256>>>(value, Wv, bv, gv, MTOT, HIDN, HIDN);

        attn_kernel<<<MTOT, 256>>>(gq, gk, gv, sw, gx, attn_ptr, write_attn);

        sgemm_bias<<<gg, 256>>>(gx, Wo, bo, out, MTOT, HIDN, HIDN);
    }
}

// round 7
// speedup vs baseline: 5.9133x; 1.0812x over previous
#include <cuda_runtime.h>
#include <cuda_bf16.h>
#include <cstdint>

// Problem constants
#define B_SZ  4
#define SEQ   4096
#define HIDN  1024
#define NH    16
#define HD    64
#define MTOT  (B_SZ * SEQ)   // 16384 tokens

// Arch-feature gate: tcgen05/TMEM only legal in arch-specific ('a') passes.
#if defined(__CUDA_ARCH__) && (defined(__CUDA_ARCH_FEAT_SM103_ALL) || defined(__CUDA_ARCH_FEAT_SM100_ALL) || defined(__CUDA_ARCH_FEAT_SM101_ALL))
#define HAS_TC 1
#else
#define HAS_TC 0
#endif

// Scratch (device globals: no allocations allowed in kernel_launch)
static __device__ float g_q[(size_t)MTOT * HIDN];
static __device__ float g_k[(size_t)MTOT * HIDN];
static __device__ float g_v[(size_t)MTOT * HIDN];
static __device__ float g_x[(size_t)MTOT * HIDN];
static __device__ __nv_bfloat16 g_wbh[(size_t)4 * HIDN * HIDN];  // weights^T hi, [4][N][K]
static __device__ __nv_bfloat16 g_wbl[(size_t)4 * HIDN * HIDN];  // weights^T lo

// ===========================================================================
// GEMM tile geometry: 128x256 tile, BK=64, TS-mode (A in TMEM), B SW128 SMEM
// ===========================================================================
#define GBM 128
#define GBN 256
#define GBK 64
#define GKD 1024
#define GNCH (GKD / GBK)          // 16 stages

#define NSTG 3                    // B smem ring depth / A TMEM ring depth
#define SM_TMEM   0
#define SM_MBAR   8               // 3 mbarriers at 8,16,24
#define SM_BUF    1024
#define BUF_STRIDE 65536          // 64 KB per stage: BH 32KB + BL 32KB
#define OFF_BL 32768
#define GEMM_SMEM_BYTES (1024 + NSTG * BUF_STRIDE)   // 197632

// TMEM: D at cols [0,256); A ring: slot s hi at 256+s*64, lo at 256+s*64+32
#define TM_A0 256

// idesc: dtype=F32(1)<<4 | atype=BF16(1)<<7 | btype=BF16(1)<<10 | (N/8)<<17 | (M/16)<<24
#define IDESC_BF16 ((1u << 4) | (1u << 7) | (1u << 10) | ((GBN / 8) << 17) | ((GBM / 16) << 24))

extern __shared__ char dynsmem[];

#if HAS_TC
// ---------------------------------------------------------------------------
// tcgen05 helpers (arch-specific pass only)
// ---------------------------------------------------------------------------
__device__ __forceinline__ uint32_t s2u(const void* p) {
    uint32_t a;
    asm("{ .reg .u64 t; cvta.to.shared.u64 t, %1; cvt.u32.u64 %0, t; }"
        : "=r"(a) : "l"(p));
    return a;
}
__device__ __forceinline__ uint64_t to_global(const void* p) {
    uint64_t g;
    asm("cvta.to.global.u64 %0, %1;" : "=l"(g) : "l"(p));
    return g;
}
__device__ __forceinline__ bool elect1() {
    uint32_t p;
    asm volatile("{ .reg .pred p; elect.sync _|p, 0xFFFFFFFF; selp.b32 %0, 1, 0, p; }"
                 : "=r"(p));
    return p != 0;
}
__device__ __forceinline__ void mbar_init(uint32_t mbar, uint32_t cnt) {
    asm volatile("mbarrier.init.shared.b64 [%0], %1;" :: "r"(mbar), "r"(cnt) : "memory");
}
__device__ __forceinline__ void mbar_wait(uint32_t mbar, uint32_t parity) {
    asm volatile(
        "{\n\t"
        ".reg .pred P;\n\t"
        "WL%=:\n\t"
        "mbarrier.try_wait.parity.acquire.cta.shared::cta.b64 P, [%0], %1, 0x989680;\n\t"
        "@P bra.uni WD%=;\n\t"
        "bra.uni WL%=;\n\t"
        "WD%=:\n\t"
        "}"
        :: "r"(mbar), "r"(parity) : "memory");
}
__device__ __forceinline__ void tmem_alloc(uint32_t smem_dst, uint32_t ncols) {
    asm volatile("tcgen05.alloc.cta_group::1.sync.aligned.shared::cta.b32 [%0], %1;"
                 :: "r"(smem_dst), "r"(ncols) : "memory");
}
__device__ __forceinline__ void tmem_relinquish() {
    asm volatile("tcgen05.relinquish_alloc_permit.cta_group::1.sync.aligned;");
}
__device__ __forceinline__ void tmem_dealloc(uint32_t tmem, uint32_t ncols) {
    asm volatile("tcgen05.dealloc.cta_group::1.sync.aligned.b32 %0, %1;"
                 :: "r"(tmem), "r"(ncols));
}
__device__ __forceinline__ void tc_commit(uint32_t mbar) {
    asm volatile("tcgen05.commit.cta_group::1.mbarrier::arrive::one.shared::cluster.b64 [%0];"
                 :: "r"(mbar) : "memory");
}
__device__ __forceinline__ void tc_fence_after() {
    asm volatile("tcgen05.fence::after_thread_sync;" ::: "memory");
}
__device__ __forceinline__ void tc_fence_before() {
    asm volatile("tcgen05.fence::before_thread_sync;" ::: "memory");
}
__device__ __forceinline__ void fence_async_smem() {
    asm volatile("fence.proxy.async.shared::cta;" ::: "memory");
}
__device__ __forceinline__ void tc_wait_ld() {
    asm volatile("tcgen05.wait::ld.sync.aligned;" ::: "memory");
}
__device__ __forceinline__ void tc_wait_st() {
    asm volatile("tcgen05.wait::st.sync.aligned;" ::: "memory");
}
__device__ __forceinline__ void cp16(uint32_t dst_smem, uint64_t src_gmem) {
    asm volatile("cp.async.cg.shared.global [%0], [%1], 16;"
                 :: "r"(dst_smem), "l"(src_gmem) : "memory");
}
__device__ __forceinline__ void cp_commit() {
    asm volatile("cp.async.commit_group;" ::: "memory");
}
__device__ __forceinline__ void cp_wait1() {
    asm volatile("cp.async.wait_group 1;" ::: "memory");
}
__device__ __forceinline__ void cp_wait0() {
    asm volatile("cp.async.wait_group 0;" ::: "memory");
}

// TS bf16 MMA, cta_group::1 (A in TMEM, B via SMEM descriptor)
__device__ __forceinline__ void mma_bf16_ts(uint32_t d_tmem, uint32_t a_tmem,
                                            uint64_t b_desc, uint32_t idesc, uint32_t en) {
    asm volatile(
        "{\n\t"
        ".reg .pred p;\n\t"
        "setp.ne.u32 p, %4, 0;\n\t"
        "tcgen05.mma.cta_group::1.kind::f16 [%0], [%1], %2, %3, {%5, %5, %5, %5}, p;\n\t"
        "}"
        :: "r"(d_tmem), "r"(a_tmem), "l"(b_desc), "r"(idesc), "r"(en), "r"(0u)
        : "memory");
}

#define TC_ST_X8(addr, r)                                                      \
    asm volatile(                                                              \
        "tcgen05.st.sync.aligned.32x32b.x8.b32 [%0], "                         \
        "{%1, %2, %3, %4, %5, %6, %7, %8};"                                    \
        :: "r"(addr),                                                          \
           "r"((r)[0]), "r"((r)[1]), "r"((r)[2]), "r"((r)[3]),                 \
           "r"((r)[4]), "r"((r)[5]), "r"((r)[6]), "r"((r)[7])                  \
        : "memory")

#define TC_LD_X32(r, addr)                                                     \
    asm volatile(                                                              \
        "tcgen05.ld.sync.aligned.32x32b.x32.b32 "                              \
        "{%0, %1, %2, %3, %4, %5, %6, %7, "                                    \
        " %8, %9, %10, %11, %12, %13, %14, %15, "                              \
        " %16, %17, %18, %19, %20, %21, %22, %23, "                            \
        " %24, %25, %26, %27, %28, %29, %30, %31}, [%32];"                     \
        : "=r"((r)[0]),  "=r"((r)[1]),  "=r"((r)[2]),  "=r"((r)[3]),           \
          "=r"((r)[4]),  "=r"((r)[5]),  "=r"((r)[6]),  "=r"((r)[7]),           \
          "=r"((r)[8]),  "=r"((r)[9]),  "=r"((r)[10]), "=r"((r)[11]),          \
          "=r"((r)[12]), "=r"((r)[13]), "=r"((r)[14]), "=r"((r)[15]),          \
          "=r"((r)[16]), "=r"((r)[17]), "=r"((r)[18]), "=r"((r)[19]),          \
          "=r"((r)[20]), "=r"((r)[21]), "=r"((r)[22]), "=r"((r)[23]),          \
          "=r"((r)[24]), "=r"((r)[25]), "=r"((r)[26]), "=r"((r)[27]),          \
          "=r"((r)[28]), "=r"((r)[29]), "=r"((r)[30]), "=r"((r)[31])           \
        : "r"(addr))

#define SWZ(o) ((o) ^ (((o) >> 3) & 0x70))

// SW128 descriptor: layout=2<<61 | version=1<<46 | SBO=64<<32 | LBO=1<<16
__device__ __forceinline__ uint64_t mkdesc(uint32_t smem_addr) {
    return 0x4000404000010000ull | ((uint64_t)(smem_addr >> 4) & 0x3FFF);
}

// Issue the B loads for stage kt into smem ring slot kt%NSTG (all 256 threads).
__device__ __forceinline__ void issue_B(uint32_t sb, uint64_t whg, uint64_t wlg,
                                        int col0, int kt, int tid) {
    const uint32_t bufu = sb + SM_BUF + (kt % NSTG) * BUF_STRIDE;
#pragma unroll
    for (int j = 0; j < 8; j++) {
        const int c  = tid + 256 * j;
        const int n  = c >> 3;
        const int k8 = c & 7;
        const uint64_t sboff = ((uint64_t)(col0 + n) * GKD + kt * GBK + k8 * 8) * 2;
        const uint32_t doff  = SWZ((uint32_t)(n * 128 + k8 * 16));
        cp16(bufu + doff, whg + sboff);
        cp16(bufu + OFF_BL + doff, wlg + sboff);
    }
    cp_commit();
}

// ---------------------------------------------------------------------------
// GEMM core: C[128,256 tile] = A @ W^T (3x bf16 split) + bias
// A fp32 [M,K] -> TMEM (hi/lo); Wh/Wl bf16 [N,K] pre-split -> SMEM ring.
// ---------------------------------------------------------------------------
__device__ __forceinline__ void gemm_core(const float* __restrict__ A,
                                          const __nv_bfloat16* __restrict__ Wh,
                                          const __nv_bfloat16* __restrict__ Wl,
                                          const float* __restrict__ bias,
                                          float* __restrict__ C)
{
    const uint32_t sb = s2u(dynsmem);
    const int tid  = threadIdx.x;
    const int row0 = blockIdx.y * GBM;
    const int col0 = blockIdx.x * GBN;

    if (tid < 32) {
        tmem_alloc(sb + SM_TMEM, 512);
        tmem_relinquish();
    }
    if (tid == 0) {
#pragma unroll
        for (int s = 0; s < NSTG; s++) mbar_init(sb + SM_MBAR + s * 8, 1);
    }
    __syncthreads();

    uint32_t tmem;
    asm volatile("ld.shared.b32 %0, [%1];" : "=r"(tmem) : "r"(sb + SM_TMEM));

    const uint64_t whg = to_global(Wh);
    const uint64_t wlg = to_global(Wl);

    // A: warps 0-3, lane-per-row (TMEM lane = tid), 64 floats per stage.
    const float* aptr = (tid < 128) ? (A + (size_t)(row0 + tid) * GKD) : A;
    const uint32_t warp_off = ((uint32_t)(tid >> 5) << 21);
    const uint32_t tmA = tmem + TM_A0 + warp_off;

    // Prologue: B(0) issued; A(0) prefetched into regs.
    issue_B(sb, whg, wlg, col0, 0, tid);
    float4 areg[16];
    if (tid < 128) {
#pragma unroll
        for (int i = 0; i < 16; i++) areg[i] = *(const float4*)(aptr + i * 4);
    }

#pragma unroll 1
    for (int kt = 0; kt < GNCH; kt++) {
        const int slot = kt % NSTG;

        // Free next ring slot: wait for MMA(kt-2) (covers A slot kt%3 too).
        if (kt >= 2) {
            const int s = kt - 2;
            mbar_wait(sb + SM_MBAR + (s % NSTG) * 8, (uint32_t)((s / NSTG) & 1));
        }

        // Issue B(kt+1) one stage ahead.
        if (kt + 1 < GNCH) issue_B(sb, whg, wlg, col0, kt + 1, tid);

        // A: split fp32 -> bf16 hi/lo, store to TMEM slot (chunks of 8 cols).
        if (tid < 128) {
#pragma unroll
            for (int ch = 0; ch < 4; ch++) {
                const float* af = (const float*)&areg[ch * 4];
                uint32_t hw[8], lw[8];
#pragma unroll
                for (int j = 0; j < 8; j++) {
                    const float x0 = af[2 * j], x1 = af[2 * j + 1];
                    __nv_bfloat162 h2 = __floats2bfloat162_rn(x0, x1);
                    const float2 hf = __bfloat1622float2(h2);
                    __nv_bfloat162 l2 = __floats2bfloat162_rn(x0 - hf.x, x1 - hf.y);
                    hw[j] = *(uint32_t*)&h2;
                    lw[j] = *(uint32_t*)&l2;
                }
                TC_ST_X8(tmA + slot * 64 + ch * 8, hw);
                TC_ST_X8(tmA + slot * 64 + 32 + ch * 8, lw);
            }
            tc_wait_st();
            tc_fence_before();
            // Prefetch next stage's A.
            if (kt + 1 < GNCH) {
                const float* ap = aptr + (kt + 1) * GBK;
#pragma unroll
                for (int i = 0; i < 16; i++) areg[i] = *(const float4*)(ap + i * 4);
            }
        }

        // B(kt) was issued last iteration: wait for it (allow B(kt+1) in flight).
        if (kt + 1 < GNCH) cp_wait1(); else cp_wait0();
        fence_async_smem();
        __syncthreads();

        // Issue 12 MMAs for stage kt: (hh, hl, lh) x 4 ksteps.
        if (tid < 32) {
            tc_fence_after();
            if (elect1()) {
                const uint32_t aBase = tmem + TM_A0 + slot * 64;
                const uint32_t bufu  = sb + SM_BUF + slot * BUF_STRIDE;
                const uint64_t dBh = mkdesc(bufu);
                const uint64_t dBl = mkdesc(bufu + OFF_BL);
#pragma unroll
                for (int ks = 0; ks < 4; ks++)
                    mma_bf16_ts(tmem, aBase + ks * 8, dBh + 2 * ks, IDESC_BF16,
                                (kt == 0 && ks == 0) ? 0u : 1u);
#pragma unroll
                for (int ks = 0; ks < 4; ks++)
                    mma_bf16_ts(tmem, aBase + ks * 8, dBl + 2 * ks, IDESC_BF16, 1u);
#pragma unroll
                for (int ks = 0; ks < 4; ks++)
                    mma_bf16_ts(tmem, aBase + 32 + ks * 8, dBh + 2 * ks, IDESC_BF16, 1u);
                tc_commit(sb + SM_MBAR + slot * 8);
            }
        }
    }

    // Drain: wait for the last stage's MMA (in-order completion => all done).
    {
        const int s = GNCH - 1;
        mbar_wait(sb + SM_MBAR + (s % NSTG) * 8, (uint32_t)((s / NSTG) & 1));
    }
    tc_fence_after();

    // Epilogue: warps 0-3 read D from TMEM, add bias, store.
    if (tid < 128) {
        const int m = row0 + tid;
        float* Crow = C + (size_t)m * HIDN + col0;
#pragma unroll
        for (int n0 = 0; n0 < GBN; n0 += 32) {
            uint32_t r[32];
            TC_LD_X32(r, tmem + n0);
            tc_wait_ld();
#pragma unroll
            for (int j = 0; j < 32; j += 4) {
                float4 o;
                o.x = __uint_as_float(r[j + 0]) + bias[col0 + n0 + j + 0];
                o.y = __uint_as_float(r[j + 1]) + bias[col0 + n0 + j + 1];
                o.z = __uint_as_float(r[j + 2]) + bias[col0 + n0 + j + 2];
                o.w = __uint_as_float(r[j + 3]) + bias[col0 + n0 + j + 3];
                *(float4*)(Crow + n0 + j) = o;
            }
        }
    }
    __syncthreads();
    if (tid < 32) tmem_dealloc(tmem, 512);
}
#endif  // HAS_TC

// Merged QKV GEMM (z selects input/weight/bias/output).
__global__ __launch_bounds__(256, 1)
void gemm_qkv(const float* __restrict__ q_in, const float* __restrict__ k_in,
              const float* __restrict__ v_in,
              const __nv_bfloat16* __restrict__ wh, const __nv_bfloat16* __restrict__ wl,
              const float* __restrict__ bq, const float* __restrict__ bk,
              const float* __restrict__ bv,
              float* __restrict__ oq, float* __restrict__ ok, float* __restrict__ ov)
{
#if HAS_TC
    const int z = blockIdx.z;
    const float* A = (z == 0) ? q_in : (z == 1) ? k_in : v_in;
    const float* bias = (z == 0) ? bq : (z == 1) ? bk : bv;
    float* C = (z == 0) ? oq : (z == 1) ? ok : ov;
    const size_t wo = (size_t)z * HIDN * HIDN;
    gemm_core(A, wh + wo, wl + wo, bias, C);
#endif
}

// Single GEMM (output projection; also the runtime capability probe).
__global__ __launch_bounds__(256, 1)
void gemm_single(const float* __restrict__ A,
                 const __nv_bfloat16* __restrict__ wh, const __nv_bfloat16* __restrict__ wl,
                 const float* __restrict__ bias, float* __restrict__ C)
{
#if HAS_TC
    gemm_core(A, wh, wl, bias, C);
#endif
}

// ===========================================================================
// Weight prep: WTh[n][k] = bf16(W[k][n]), WTl = bf16(residual). 4 matrices.
// ===========================================================================
__global__ __launch_bounds__(256)
void prep_weights(const float* __restrict__ s0, const float* __restrict__ s1,
                  const float* __restrict__ s2, const float* __restrict__ s3,
                  __nv_bfloat16* __restrict__ dh, __nv_bfloat16* __restrict__ dl)
{
    __shared__ float t[32][33];
    const float* src = (blockIdx.z == 0) ? s0 : (blockIdx.z == 1) ? s1
                     : (blockIdx.z == 2) ? s2 : s3;
    const size_t zo = (size_t)blockIdx.z * HIDN * HIDN;
    const int x0 = blockIdx.x * 32, y0 = blockIdx.y * 32;   // x: n, y: k
    const int tx = threadIdx.x & 31, ty0 = threadIdx.x >> 5;
#pragma unroll
    for (int i = 0; i < 4; i++) {
        const int ty = ty0 + i * 8;
        t[ty][tx] = src[(size_t)(y0 + ty) * HIDN + x0 + tx];
    }
    __syncthreads();
#pragma unroll
    for (int i = 0; i < 4; i++) {
        const int ty = ty0 + i * 8;
        const float val = t[tx][ty];
        const __nv_bfloat16 h = __float2bfloat16_rn(val);
        const __nv_bfloat16 l = __float2bfloat16_rn(val - __bfloat162float(h));
        const size_t di = zo + (size_t)(x0 + ty) * HIDN + (y0 + tx);
        dh[di] = h;
        dl[di] = l;
    }
}

// ===========================================================================
// Fallback SGEMM (fp32, proven path) — compiles on every arch.
// ===========================================================================
#define BM 128
#define BN 128
#define BK 16

__global__ __launch_bounds__(256, 2)
void sgemm_bias(const float* __restrict__ A, const float* __restrict__ W,
                const float* __restrict__ bias, float* __restrict__ C,
                int M, int N, int K)
{
    __shared__ float As[2][BK][BM];
    __shared__ float Bs[2][BK][BN];

    const int tid = threadIdx.x;
    const int tx  = tid & 15;
    const int ty  = tid >> 4;
    const int row0 = blockIdx.y * BM;
    const int col0 = blockIdx.x * BN;

    const int a_r = tid >> 2;
    const int a_k = (tid & 3) << 2;
    const int b_r = tid >> 5;
    const int b_c = (tid & 31) << 2;

    const float* Ab = A + (size_t)row0 * K;

    float acc[8][8];
#pragma unroll
    for (int i = 0; i < 8; i++)
#pragma unroll
        for (int j = 0; j < 8; j++) acc[i][j] = 0.f;

    {
        float4 a0 = *(const float4*)(Ab + (size_t)a_r * K + a_k);
        float4 a1 = *(const float4*)(Ab + (size_t)(a_r + 64) * K + a_k);
        float4 w0 = *(const float4*)(W + (size_t)b_r * N + col0 + b_c);
        float4 w1 = *(const float4*)(W + (size_t)(b_r + 8) * N + col0 + b_c);
        As[0][a_k + 0][a_r] = a0.x; As[0][a_k + 1][a_r] = a0.y;
        As[0][a_k + 2][a_r] = a0.z; As[0][a_k + 3][a_r] = a0.w;
        As[0][a_k + 0][a_r + 64] = a1.x; As[0][a_k + 1][a_r + 64] = a1.y;
        As[0][a_k + 2][a_r + 64] = a1.z; As[0][a_k + 3][a_r + 64] = a1.w;
        *(float4*)&Bs[0][b_r][b_c]     = w0;
        *(float4*)&Bs[0][b_r + 8][b_c] = w1;
    }
    __syncthreads();

    const int NT = K / BK;
    for (int kt = 0; kt < NT; kt++) {
        const int cur = kt & 1;

        float4 a0, a1, w0, w1;
        const bool more = (kt + 1 < NT);
        if (more) {
            const float* Ap = Ab + (size_t)(kt + 1) * BK;
            a0 = *(const float4*)(Ap + (size_t)a_r * K + a_k);
            a1 = *(const float4*)(Ap + (size_t)(a_r + 64) * K + a_k);
            const float* Wp = W + (size_t)(kt + 1) * BK * N + col0;
            w0 = *(const float4*)(Wp + (size_t)b_r * N + b_c);
            w1 = *(const float4*)(Wp + (size_t)(b_r + 8) * N + b_c);
        }

#pragma unroll
        for (int kk = 0; kk < BK; kk++) {
            float ar[8], br[8];
            *(float4*)(ar)     = *(const float4*)&As[cur][kk][ty * 8];
            *(float4*)(ar + 4) = *(const float4*)&As[cur][kk][ty * 8 + 4];
            *(float4*)(br)     = *(const float4*)&Bs[cur][kk][tx * 8];
            *(float4*)(br + 4) = *(const float4*)&Bs[cur][kk][tx * 8 + 4];
#pragma unroll
            for (int i = 0; i < 8; i++)
#pragma unroll
                for (int j = 0; j < 8; j++)
                    acc[i][j] += ar[i] * br[j];
        }

        if (more) {
            const int nxt = cur ^ 1;
            As[nxt][a_k + 0][a_r] = a0.x; As[nxt][a_k + 1][a_r] = a0.y;
            As[nxt][a_k + 2][a_r] = a0.z; As[nxt][a_k + 3][a_r] = a0.w;
            As[nxt][a_k + 0][a_r + 64] = a1.x; As[nxt][a_k + 1][a_r + 64] = a1.y;
            As[nxt][a_k + 2][a_r + 64] = a1.z; As[nxt][a_k + 3][a_r + 64] = a1.w;
            *(float4*)&Bs[nxt][b_r][b_c]     = w0;
            *(float4*)&Bs[nxt][b_r + 8][b_c] = w1;
        }
        __syncthreads();
    }

#pragma unroll
    for (int i = 0; i < 8; i++) {
        const size_t r = (size_t)(row0 + ty * 8 + i);
#pragma unroll
        for (int j4 = 0; j4 < 8; j4 += 4) {
            const int c = col0 + tx * 8 + j4;
            float4 o;
            o.x = acc[i][j4 + 0] + bias[c + 0];
            o.y = acc[i][j4 + 1] + bias[c + 1];
            o.z = acc[i][j4 + 2] + bias[c + 2];
            o.w = acc[i][j4 + 3] + bias[c + 3];
            *(float4*)&C[r * N + c] = o;
        }
    }
}

// ===========================================================================
// Per-token attention over the HEADS axis.
// ===========================================================================
#define PD 68

__global__ __launch_bounds__(256)
void attn_kernel(const float* __restrict__ q, const float* __restrict__ k,
                 const float* __restrict__ v, const float* __restrict__ sw,
                 float* __restrict__ xperm, float* __restrict__ attn_out,
                 int write_attn)
{
    __shared__ float sq[NH][PD], sk[NH][PD], sv[NH][PD];
    __shared__ float s_qk[NH][NH];
    __shared__ float s_qn2[NH], s_kn2[NH];
    __shared__ float s_at[NH][NH + 1];

    const int t   = blockIdx.x;
    const int b   = t >> 12;
    const int s   = t & 4095;
    const int tid = threadIdx.x;
    const size_t base = (size_t)t * HIDN;

    {
        const int row = tid >> 4;
        const int col = (tid & 15) << 2;
        *(float4*)&sq[row][col] = *(const float4*)(q + base + row * HD + col);
        *(float4*)&sk[row][col] = *(const float4*)(k + base + row * HD + col);
        *(float4*)&sv[row][col] = *(const float4*)(v + base + row * HD + col);
    }
    __syncthreads();

    if (tid < 32) {
        const int i = tid & 15;
        const float* p = (tid < 16) ? sq[i] : sk[i];
        float ss = 0.f;
#pragma unroll
        for (int d = 0; d < HD; d++) ss += p[d] * p[d];
        if (tid < 16) s_qn2[i] = ss; else s_kn2[i] = ss;
    }
    {
        const int i = tid >> 4, j = tid & 15;
        float dot = 0.f;
#pragma unroll
        for (int d = 0; d < HD; d++) dot += sq[i][d] * sk[j][d];
        s_qk[i][j] = dot;
    }
    __syncthreads();

    if (tid < NH) {
        float w0, w1, w2;
        {
            const float x0 = sw[0], x1 = sw[1], x2 = sw[2];
            const float m  = fmaxf(x0, fmaxf(x1, x2));
            const float e0 = expf(x0 - m), e1 = expf(x1 - m), e2 = expf(x2 - m);
            const float inv = 1.f / (e0 + e1 + e2);
            w0 = e0 * inv; w1 = e1 * inv; w2 = e2 * inv;
        }
        const int i = tid;
        const float qn2 = s_qn2[i];
        const float qn  = sqrtf(qn2);
        float sc[NH];
        float mx = -1e30f;
#pragma unroll
        for (int j = 0; j < NH; j++) {
            const float qkv  = s_qk[i][j];
            const float kn2  = s_kn2[j];
            const float dotv = qkv * 0.125f;
            const float cosv = qkv / fmaxf(qn * sqrtf(kn2), 1e-8f);
            const float d2   = fmaxf(qn2 + kn2 - 2.f * qkv, 0.f);
            const float dstv = -sqrtf(d2);
            const float scv  = w0 * dotv + w1 * cosv + w2 * dstv;
            sc[j] = scv;
            mx = fmaxf(mx, scv);
        }
        float ssum = 0.f;
#pragma unroll
        for (int j = 0; j < NH; j++) { const float e = expf(sc[j] - mx); sc[j] = e; ssum += e; }
        const float inv = 1.f / ssum;
#pragma unroll
        for (int j = 0; j < NH; j++) {
            const float a = sc[j] * inv;
            s_at[i][j] = a;
            if (write_attn)
                attn_out[(size_t)t * (NH * NH) + i * NH + j] = a;
        }
    }
    __syncthreads();

    {
        const int i  = tid >> 4;
        const int db = (tid & 15) << 2;
        float4 o = make_float4(0.f, 0.f, 0.f, 0.f);
#pragma unroll
        for (int j = 0; j < NH; j++) {
            const float a = s_at[i][j];
            const float4 vv = *(const float4*)&sv[j][db];
            o.x += a * vv.x; o.y += a * vv.y; o.z += a * vv.z; o.w += a * vv.w;
        }
        const size_t dst = (size_t)b * ((size_t)SEQ * HIDN)
                         + (size_t)((i << 8) + (s >> 4)) * HIDN
                         + (size_t)((s & 15) << 6) + db;
        *(float4*)&xperm[dst] = o;
    }
}

// ===========================================================================
extern "C" void kernel_launch(void* const* d_in, const int* in_sizes, int n_in,
                              void* d_out, int out_size)
{
    const float* query = (const float*)d_in[0];
    const float* key_  = (const float*)d_in[1];
    const float* value = (const float*)d_in[2];
    const float* Wq    = (const float*)d_in[3];
    const float* bq    = (const float*)d_in[4];
    const float* Wk    = (const float*)d_in[5];
    const float* bk    = (const float*)d_in[6];
    const float* Wv    = (const float*)d_in[7];
    const float* bv    = (const float*)d_in[8];
    const float* Wo    = (const float*)d_in[9];
    const float* bo    = (const float*)d_in[10];
    const float* sw    = (const float*)d_in[11];
    float* out = (float*)d_out;

    float *gq, *gk, *gv, *gx;
    __nv_bfloat16 *gwh, *gwl;
    cudaGetSymbolAddress((void**)&gq,  g_q);
    cudaGetSymbolAddress((void**)&gk,  g_k);
    cudaGetSymbolAddress((void**)&gv,  g_v);
    cudaGetSymbolAddress((void**)&gx,  g_x);
    cudaGetSymbolAddress((void**)&gwh, g_wbh);
    cudaGetSymbolAddress((void**)&gwl, g_wbl);

    const long long main_elems = (long long)MTOT * HIDN;
    const long long attn_elems = (long long)MTOT * NH * NH;
    const int write_attn = ((long long)out_size >= main_elems + attn_elems) ? 1 : 0;
    float* attn_ptr = out + main_elems;

    // Capability probe: stubbed (non-'a' pass) kernel uses only a few regs.
    cudaFuncAttributes fa;
    fa.numRegs = 0;
    cudaError_t perr = cudaFuncGetAttributes(&fa, gemm_single);
    const bool use_tc = (perr == cudaSuccess) && (fa.numRegs >= 40);

    if (use_tc) {
        cudaFuncSetAttribute(gemm_qkv, cudaFuncAttributeMaxDynamicSharedMemorySize,
                             GEMM_SMEM_BYTES);
        cudaFuncSetAttribute(gemm_single, cudaFuncAttributeMaxDynamicSharedMemorySize,
                             GEMM_SMEM_BYTES);

        // Transpose + bf16-split all 4 weight matrices
        prep_weights<<<dim3(32, 32, 4), 256>>>(Wq, Wk, Wv, Wo, gwh, gwl);

        const size_t WSZ = (size_t)HIDN * HIDN;
        dim3 gq3(HIDN / GBN, MTOT / GBM, 3);   // (4, 128, 3)
        dim3 gg1(HIDN / GBN, MTOT / GBM);

        gemm_qkv<<<gq3, 256, GEMM_SMEM_BYTES>>>(query, key_, value, gwh, gwl,
                                                bq, bk, bv, gq, gk, gv);

        attn_kernel<<<MTOT, 256>>>(gq, gk, gv, sw, gx, attn_ptr, write_attn);

        gemm_single<<<gg1, 256, GEMM_SMEM_BYTES>>>(gx, gwh + 3 * WSZ, gwl + 3 * WSZ,
                                                   bo, out);
    } else {
        // Fallback: proven fp32 path.
        dim3 gg(HIDN / BN, MTOT / BM);
        sgemm_bias<<<gg, 256>>>(query, Wq, bq, gq, MTOT, HIDN, HIDN);
        sgemm_bias<<<gg, 256>>>(key_,  Wk, bk, gk, MTOT, HIDN, HIDN);
        sgemm_bias<<<gg, 256>>>(value, Wv, bv, gv, MTOT, HIDN, HIDN);

        attn_kernel<<<MTOT, 256>>>(gq, gk, gv, sw, gx, attn_ptr, write_attn);

        sgemm_bias<<<gg, 256>>>(gx, Wo, bo, out, MTOT, HIDN, HIDN);
    }
}